// round 11
// baseline (speedup 1.0000x reference)
#include <cuda_runtime.h>
#include <cstdint>

typedef unsigned long long ull;

#define RELK 73728

// ---------------- smem layout (float offsets) ----------------
#define SM_MI     0        // 96*100
#define SM_RELSUM 9600     // 9216
#define SM_TDUP   18816    // 12288 floats = 6144 ull
#define SM_QKVT   31104    // 24*100
#define SM_WQT    33504    // 24*100
#define SM_LG     35904    // 2304
#define SM_LB     38208    // 2304
#define SM_GPART  40512    // 16*768 = 12288
#define SM_XTS    52800    // 96
#define SM_VTR4   52896    // 384
#define SM_VTRF   53280    // 96
#define SM_XW     53376    // 32
#define SM_BQ     53408    // 32
#define SM_B2S    53440    // 96
#define SM_RED    53536    // 32
#define STEP_SMEM_FLOATS 53568
#define STEP_SMEM_BYTES (STEP_SMEM_FLOATS * 4)   // 214,272 B

__device__ float g_C2[(size_t)8 * 9216 * 64];
__device__ float g_cconst[64];
__device__ float g_relsum0[9216];
__device__ float g_z0[64];
__device__ float g_zbuf[(size_t)2048 * 64];
__device__ float g_relhist[(size_t)16 * 128 * RELK];

__device__ __forceinline__ ull pk2(float x, float y) {
    ull r;
    asm("mov.b64 %0, {%1, %2};" : "=l"(r) : "f"(x), "f"(y));
    return r;
}
__device__ __forceinline__ void fma2(ull& d, ull a, ull b) {
    asm("fma.rn.f32x2 %0, %1, %2, %0;" : "+l"(d) : "l"(a), "l"(b));
}
__device__ __forceinline__ void add2(ull& d, ull a) {
    asm("add.rn.f32x2 %0, %0, %1;" : "+l"(d) : "l"(a));
}
__device__ __forceinline__ void upk2(float& lo, float& hi, ull v) {
    asm("mov.b64 {%0, %1}, %2;" : "=f"(lo), "=f"(hi) : "l"(v));
}

// ---- combined init: relsum0 + zbuf zero + z0 zero (launch #1) ----
__global__ void init_kernel(const float* __restrict__ rb) {
    int idx = blockIdx.x * 256 + threadIdx.x;   // grid 512 -> 131072 threads
    if (idx < 9216) {
        float s = 0.f;
#pragma unroll
        for (int n = 0; n < 8; ++n) s += rb[n * 9216 + idx];
        g_relsum0[idx] = s;
    }
    g_zbuf[idx] = 0.f;
    if (idx < 64) g_z0[idx] = 0.f;
}

__global__ void __launch_bounds__(256, 1) c2_kernel(const float* __restrict__ Wr,
                                                    const float* __restrict__ W3) {
    __shared__ float Wrs[32 * 96];
    __shared__ float W3s[96 * 64];
    const int tid = threadIdx.x;
    const int de0 = blockIdx.x * 32;
    const int n = blockIdx.y;
    for (int p = tid; p < 3072; p += 256) Wrs[p] = Wr[de0 * 96 + p];
    for (int p = tid; p < 6144; p += 256) W3s[p] = W3[n * 6144 + p];
    __syncthreads();
    const int o = tid & 63, de_b = tid >> 6;
    float acc[8];
#pragma unroll
    for (int i = 0; i < 8; ++i) acc[i] = 0.f;
    for (int r = 0; r < 96; ++r) {
        float bv = W3s[r * 64 + o];
#pragma unroll
        for (int i = 0; i < 8; ++i)
            acc[i] = fmaf(Wrs[(de_b + 4 * i) * 96 + r], bv, acc[i]);
    }
#pragma unroll
    for (int i = 0; i < 8; ++i) {
        int de = de0 + de_b + 4 * i;
        g_C2[((size_t)n * 9216 + de) * 64 + o] = acc[i];
    }
}

__global__ void cconst_kernel(const float* __restrict__ br,
                              const float* __restrict__ W3,
                              const float* __restrict__ b3) {
    int o = threadIdx.x;
    float acc = b3[o];
    for (int nr = 0; nr < 768; ++nr)
        acc = fmaf(br[nr % 96], W3[nr * 64 + o], acc);
    g_cconst[o] = acc;
}

__global__ void __launch_bounds__(256, 1) z0_kernel(const float* __restrict__ rb) {
    __shared__ float part[256];
    const int o = threadIdx.x & 63, kk = threadIdx.x >> 6;
    const size_t kbase = (size_t)blockIdx.x * 1152;
    float acc = 0.f;
    for (int k = kk; k < 1152; k += 4) {
        size_t kg = kbase + k;
        acc = fmaf(rb[kg], g_C2[kg * 64 + o], acc);
    }
    part[threadIdx.x] = acc;
    __syncthreads();
    if (threadIdx.x < 64) {
        float s = part[o] + part[64 + o] + part[128 + o] + part[192 + o];
        atomicAdd(&g_z0[o], s);
    }
}

// ---------------- phase 1: persistent recurrent kernel (unchanged, measured) --
__global__ void __launch_bounds__(384, 1) step_kernel(
    const float* __restrict__ x, const float* __restrict__ Wqkv,
    const float* __restrict__ bqkv, const float* __restrict__ ln_g,
    const float* __restrict__ ln_b, const float* __restrict__ pa1,
    const float* __restrict__ pa2, const float* __restrict__ pa3,
    const float* __restrict__ W2, const float* __restrict__ b2,
    const float* __restrict__ item_bias)
{
    extern __shared__ float sm[];
    float* Mi     = sm + SM_MI;
    float* relsum = sm + SM_RELSUM;
    ull*   tdup   = (ull*)(sm + SM_TDUP);
    float* qkvT   = sm + SM_QKVT;
    float* WqT    = sm + SM_WQT;
    float* lg     = sm + SM_LG;
    float* lb     = sm + SM_LB;
    float* Gpart  = sm + SM_GPART;
    float* xts    = sm + SM_XTS;
    float* vtr4   = sm + SM_VTR4;
    float* vtrF   = sm + SM_VTRF;
    float* xw     = sm + SM_XW;
    float* bq     = sm + SM_BQ;
    float* b2s    = sm + SM_B2S;
    float* red    = sm + SM_RED;

    const int tid = threadIdx.x;
    const int b = blockIdx.x;
    const float a1v = *pa1, a2v = *pa2, a3v = *pa3;

    for (int idx = tid; idx < 2304; idx += 384) {
        int f = idx / 24, h = idx % 24;
        WqT[h * 100 + f] = Wqkv[idx];
        lg[idx] = ln_g[idx];
        lb[idx] = ln_b[idx];
    }
    if (tid < 24) bq[tid] = bqkv[tid];
    if (tid < 96) b2s[tid] = b2[tid];
    for (int idx = tid; idx < 9216; idx += 384) {
        Mi[(idx / 96) * 100 + (idx % 96)] = item_bias[idx];
        relsum[idx] = g_relsum0[idx];
    }
    __syncthreads();

    for (int t = 0; t < 16; ++t) {
        if (tid < 96) xts[tid] = x[(t * 128 + b) * 96 + tid];
        __syncthreads();

        for (int idx = tid; idx < 9216; idx += 384) {
            int d = idx / 96, f = idx % 96;
            Mi[d * 100 + f] = fmaf(xts[d], xts[f], Mi[d * 100 + f]);
        }
        __syncthreads();

        {
            int f = tid % 96, q = tid / 96;
            int d0 = q * 24;
            float acc = 0.f;
#pragma unroll 6
            for (int d = d0; d < d0 + 24; ++d)
                acc = fmaf(Mi[d * 100 + f], relsum[d * 96 + f], acc);
            vtr4[q * 96 + f] = acc;
        }
        if (tid < 24) {
            float acc = 0.f;
            for (int f = 0; f < 96; ++f)
                acc = fmaf(xts[f], WqT[tid * 100 + f], acc);
            xw[tid] = acc;
        }
        __syncthreads();
        if (tid < 96)
            vtrF[tid] = vtr4[tid] + vtr4[96 + tid] + vtr4[192 + tid] + vtr4[288 + tid];
        __syncthreads();

        float s1 = 0.f, s2 = 0.f;
        {
            const int hg = tid / 96;
            const int d  = tid % 96;
            const int h0 = hg * 6;
            ull acc[6][2];
#pragma unroll
            for (int i = 0; i < 6; ++i) { acc[i][0] = 0ull; acc[i][1] = 0ull; }
#pragma unroll 6
            for (int fq = 0; fq < 24; ++fq) {
                ulonglong2 m2 = *(const ulonglong2*)&Mi[d * 100 + 4 * fq];
#pragma unroll
                for (int hh = 0; hh < 6; ++hh) {
                    ulonglong2 w2v = *(const ulonglong2*)&WqT[(h0 + hh) * 100 + 4 * fq];
                    fma2(acc[hh][0], m2.x, w2v.x);
                    fma2(acc[hh][1], m2.y, w2v.y);
                }
            }
            const float vtrd = vtrF[d];
#pragma unroll
            for (int hh = 0; hh < 6; ++hh) {
                float l0, h0f, l1, h1f;
                upk2(l0, h0f, acc[hh][0]);
                upk2(l1, h1f, acc[hh][1]);
                int h = h0 + hh;
                float v = (l0 + h0f) + (l1 + h1f) + bq[h] + a2v * vtrd * xw[h];
                qkvT[h * 100 + d] = v;
                s1 += v;
                s2 = fmaf(v, v, s2);
            }
        }
#pragma unroll
        for (int o = 16; o > 0; o >>= 1) {
            s1 += __shfl_down_sync(0xffffffffu, s1, o);
            s2 += __shfl_down_sync(0xffffffffu, s2, o);
        }
        if ((tid & 31) == 0) { red[(tid >> 5) * 2] = s1; red[(tid >> 5) * 2 + 1] = s2; }
        __syncthreads();
        if (tid == 0) {
            float S = 0.f, SS = 0.f;
            for (int w = 0; w < 12; ++w) { S += red[w * 2]; SS += red[w * 2 + 1]; }
            float mu = S * (1.f / 2304.f);
            float var = SS * (1.f / 2304.f) - mu * mu;
            red[30] = mu;
            red[31] = rsqrtf(var + 1e-5f);
        }
        __syncthreads();
        const float mu = red[30], rstd = red[31];

        for (int idx = tid; idx < 2304; idx += 384) {
            int h = idx / 96, d = idx % 96;
            float v = qkvT[h * 100 + d];
            qkvT[h * 100 + d] = (v - mu) * rstd * lg[d * 24 + h] + lb[d * 24 + h];
        }
        __syncthreads();

        for (int idx = tid; idx < 6144; idx += 384) {
            int j = idx & 7, d = (idx >> 3) % 96, n = idx / 768;
            float p = qkvT[n * 100 + d] * qkvT[(8 + j) * 100 + d];
            float e = __expf(2.f * p);
            float tv = 1.f - 2.f / (e + 1.f);
            tdup[idx] = pk2(tv, tv);
        }
        __syncthreads();

        {
            const int fp2 = tid % 24;
            const int g   = tid / 24;
            const int f0  = 4 * fp2;
            ull acc[8][2];
#pragma unroll
            for (int j = 0; j < 8; ++j) { acc[j][0] = 0ull; acc[j][1] = 0ull; }
            const float* w2p = W2 + (size_t)(g * 48) * 96 + f0;
            const ulonglong2* tp = (const ulonglong2*)&tdup[(g * 48) * 8];
#pragma unroll 4
            for (int m = 0; m < 48; ++m) {
                float4 wv = *(const float4*)&w2p[(size_t)m * 96];
                ull w01 = pk2(wv.x, wv.y);
                ull w23 = pk2(wv.z, wv.w);
                ulonglong2 t01 = tp[m * 4 + 0];
                ulonglong2 t23 = tp[m * 4 + 1];
                ulonglong2 t45 = tp[m * 4 + 2];
                ulonglong2 t67 = tp[m * 4 + 3];
                fma2(acc[0][0], t01.x, w01); fma2(acc[0][1], t01.x, w23);
                fma2(acc[1][0], t01.y, w01); fma2(acc[1][1], t01.y, w23);
                fma2(acc[2][0], t23.x, w01); fma2(acc[2][1], t23.x, w23);
                fma2(acc[3][0], t23.y, w01); fma2(acc[3][1], t23.y, w23);
                fma2(acc[4][0], t45.x, w01); fma2(acc[4][1], t45.x, w23);
                fma2(acc[5][0], t45.y, w01); fma2(acc[5][1], t45.y, w23);
                fma2(acc[6][0], t67.x, w01); fma2(acc[6][1], t67.x, w23);
                fma2(acc[7][0], t67.y, w01); fma2(acc[7][1], t67.y, w23);
            }
#pragma unroll
            for (int j = 0; j < 8; ++j)
                *(ulonglong2*)&Gpart[g * 768 + j * 96 + f0] =
                    make_ulonglong2(acc[j][0], acc[j][1]);
        }
        __syncthreads();
        for (int idx = tid; idx < 768; idx += 384) {
            float s = Gpart[idx];
#pragma unroll
            for (int g2 = 1; g2 < 16; ++g2) s += Gpart[g2 * 768 + idx];
            Gpart[idx] = s;
        }
        __syncthreads();

        {
            const int e = tid >> 2, part = tid & 3;
            const int f0b = part * 24;
            ull vp[8];
#pragma unroll
            for (int j = 0; j < 8; ++j) {
                float ve = qkvT[(16 + j) * 100 + e];
                vp[j] = pk2(ve, ve);
            }
#pragma unroll 3
            for (int q = 0; q < 12; ++q) {
                int f0 = f0b + q * 2;
                ull acc = 0ull;
#pragma unroll
                for (int j = 0; j < 8; ++j)
                    fma2(acc, vp[j], *(const ull*)&Gpart[j * 96 + f0]);
                float lo, hi;
                upk2(lo, hi, acc);
                Mi[e * 100 + f0]     = fmaf(a3v, lo + b2s[f0],     Mi[e * 100 + f0]);
                Mi[e * 100 + f0 + 1] = fmaf(a3v, hi + b2s[f0 + 1], Mi[e * 100 + f0 + 1]);
            }
        }

        {
            const int ep = tid % 24;
            const int g  = tid / 24;
            const int e0 = 4 * ep;
            ull vP[8][2];
#pragma unroll
            for (int j = 0; j < 8; ++j) {
                ulonglong2 tv = *(const ulonglong2*)&qkvT[(16 + j) * 100 + e0];
                vP[j][0] = tv.x;
                vP[j][1] = tv.y;
            }
            float* relo = g_relhist + ((size_t)t * 128 + b) * RELK;
            ull racc[6][2];
#pragma unroll
            for (int mm = 0; mm < 6; ++mm) { racc[mm][0] = 0ull; racc[mm][1] = 0ull; }
#pragma unroll 4
            for (int it = g; it < 768; it += 16) {
                const ulonglong2* tp = (const ulonglong2*)&tdup[it * 8];
                ulonglong2 t01 = tp[0], t23 = tp[1], t45 = tp[2], t67 = tp[3];
                ull a0 = 0ull, a1_ = 0ull;
                fma2(a0, t01.x, vP[0][0]); fma2(a1_, t01.x, vP[0][1]);
                fma2(a0, t01.y, vP[1][0]); fma2(a1_, t01.y, vP[1][1]);
                fma2(a0, t23.x, vP[2][0]); fma2(a1_, t23.x, vP[2][1]);
                fma2(a0, t23.y, vP[3][0]); fma2(a1_, t23.y, vP[3][1]);
                fma2(a0, t45.x, vP[4][0]); fma2(a1_, t45.x, vP[4][1]);
                fma2(a0, t45.y, vP[5][0]); fma2(a1_, t45.y, vP[5][1]);
                fma2(a0, t67.x, vP[6][0]); fma2(a1_, t67.x, vP[6][1]);
                fma2(a0, t67.y, vP[7][0]); fma2(a1_, t67.y, vP[7][1]);
                *(ulonglong2*)&relo[(size_t)it * 96 + e0] = make_ulonglong2(a0, a1_);
                int mm = (it >> 4) % 6;
                add2(racc[mm][0], a0);
                add2(racc[mm][1], a1_);
            }
            const ull a1P = pk2(a1v, a1v);
#pragma unroll
            for (int mm = 0; mm < 6; ++mm) {
                int d = g + 16 * mm;
                ulonglong2 old = *(const ulonglong2*)&relsum[d * 96 + e0];
                fma2(racc[mm][0], a1P, old.x);
                fma2(racc[mm][1], a1P, old.y);
                *(ulonglong2*)&relsum[d * 96 + e0] =
                    make_ulonglong2(racc[mm][0], racc[mm][1]);
            }
        }
        __syncthreads();
    }
}

// ---------------- phase 2: zbuf += R0hist @ C2  (M=2048, K=73728, N=64) ------
// M-tile 128, k-split 24 (grid 16x24), 256 thr, 3 CTAs/SM for latency hiding.
#define G2_AS_ULL (128 * 34)
#define G2_SMEM_BYTES (G2_AS_ULL * 8 + 32 * 64 * 4)   // 34816 + 8192 = 43008
__global__ void __launch_bounds__(256, 3) out_gemm_kernel() {
    extern __shared__ ull smu[];
    ull* As2 = smu;                          // [128][34] (dup pairs)
    float* Bs = (float*)(smu + G2_AS_ULL);   // [32][64]
    const int tid = threadIdx.x;
    const int m0 = blockIdx.x * 128;
    const int k0 = blockIdx.y * 3072;
    const int cg = tid & 7, rg = tid >> 3;   // rg 0..31, cg = o-octet
    ull acc[4][4];
#pragma unroll
    for (int i = 0; i < 4; ++i)
#pragma unroll
        for (int j = 0; j < 4; ++j) acc[i][j] = 0ull;

    for (int kc = 0; kc < 3072; kc += 32) {
#pragma unroll
        for (int it = 0; it < 4; ++it) {
            int idx = it * 256 + tid;
            int r = idx >> 3, q = idx & 7;
            float4 v = *(const float4*)&g_relhist[(size_t)(m0 + r) * RELK + k0 + kc + 4 * q];
            ulonglong2* dst = (ulonglong2*)&As2[r * 34 + 4 * q];
            dst[0] = make_ulonglong2(pk2(v.x, v.x), pk2(v.y, v.y));
            dst[1] = make_ulonglong2(pk2(v.z, v.z), pk2(v.w, v.w));
        }
#pragma unroll
        for (int it = 0; it < 2; ++it) {
            int idx = it * 256 + tid;
            int kr = idx >> 4, q = idx & 15;
            *(float4*)&Bs[kr * 64 + 4 * q] =
                *(const float4*)&g_C2[(size_t)(k0 + kc + kr) * 64 + 4 * q];
        }
        __syncthreads();
#pragma unroll
        for (int k = 0; k < 32; ++k) {
            ulonglong2 bA = *(const ulonglong2*)&Bs[k * 64 + cg * 8];
            ulonglong2 bB = *(const ulonglong2*)&Bs[k * 64 + cg * 8 + 4];
#pragma unroll
            for (int i = 0; i < 4; ++i) {
                ull aP = As2[(rg + 32 * i) * 34 + k];
                fma2(acc[i][0], aP, bA.x);
                fma2(acc[i][1], aP, bA.y);
                fma2(acc[i][2], aP, bB.x);
                fma2(acc[i][3], aP, bB.y);
            }
        }
        __syncthreads();
    }
#pragma unroll
    for (int i = 0; i < 4; ++i) {
        int m = m0 + rg + 32 * i;
#pragma unroll
        for (int j = 0; j < 4; ++j) {
            float lo, hi;
            upk2(lo, hi, acc[i][j]);
            atomicAdd(&g_zbuf[(size_t)m * 64 + cg * 8 + 2 * j], lo);
            atomicAdd(&g_zbuf[(size_t)m * 64 + cg * 8 + 2 * j + 1], hi);
        }
    }
}

__global__ void scan_kernel(float* __restrict__ out, const float* __restrict__ pa1) {
    const int b = blockIdx.x;
    const int o = threadIdx.x;
    const float a1v = *pa1;
    const float z0o = g_z0[o], cc = g_cconst[o];
    float acc = 0.f, p = 1.f;
#pragma unroll
    for (int t = 0; t < 16; ++t) {
        p *= a1v;
        acc = fmaf(a1v, acc, g_zbuf[(size_t)(t * 128 + b) * 64 + o]);
        out[(size_t)(t * 128 + b) * 64 + o] = fmaf(p, z0o, acc + cc);
    }
}

extern "C" void kernel_launch(void* const* d_in, const int* in_sizes, int n_in,
                              void* d_out, int out_size) {
    const float* x         = (const float*)d_in[0];
    const float* Wqkv      = (const float*)d_in[1];
    const float* bqkv      = (const float*)d_in[2];
    const float* ln_g      = (const float*)d_in[3];
    const float* ln_b      = (const float*)d_in[4];
    const float* a1        = (const float*)d_in[5];
    const float* a2        = (const float*)d_in[6];
    const float* a3        = (const float*)d_in[7];
    const float* W2        = (const float*)d_in[8];
    const float* b2        = (const float*)d_in[9];
    const float* Wr        = (const float*)d_in[10];
    const float* br        = (const float*)d_in[11];
    const float* W3        = (const float*)d_in[12];
    const float* b3        = (const float*)d_in[13];
    const float* item_bias = (const float*)d_in[14];
    const float* rel_bias  = (const float*)d_in[15];
    float* out = (float*)d_out;

    cudaFuncSetAttribute(step_kernel, cudaFuncAttributeMaxDynamicSharedMemorySize,
                         STEP_SMEM_BYTES);
    cudaFuncSetAttribute(out_gemm_kernel, cudaFuncAttributeMaxDynamicSharedMemorySize,
                         G2_SMEM_BYTES);

    // Order chosen so out_gemm_kernel is launch #4 (ncu captures the 4th).
    init_kernel<<<512, 256>>>(rel_bias);                                   // 1
    step_kernel<<<128, 384, STEP_SMEM_BYTES>>>(x, Wqkv, bqkv, ln_g, ln_b,
                                               a1, a2, a3, W2, b2, item_bias); // 2
    c2_kernel<<<dim3(288, 8), 256>>>(Wr, W3);                              // 3
    out_gemm_kernel<<<dim3(16, 24), 256, G2_SMEM_BYTES>>>();               // 4 (profiled)
    z0_kernel<<<64, 256>>>(rel_bias);                                      // 5
    cconst_kernel<<<1, 64>>>(br, W3, b3);                                  // 6
    scan_kernel<<<128, 64>>>(out, a1);                                     // 7
}

// round 13
// speedup vs baseline: 1.5845x; 1.5845x over previous
#include <cuda_runtime.h>
#include <cuda_bf16.h>
#include <cstdint>

typedef unsigned long long ull;

#define RELK 73728

// ---------------- smem layout for step_kernel (float offsets) ----------------
#define SM_MI     0        // 96*100
#define SM_RELSUM 9600     // 9216
#define SM_TDUP   18816    // 12288 floats = 6144 ull
#define SM_QKVT   31104    // 24*100
#define SM_WQT    33504    // 24*100
#define SM_LG     35904    // 2304
#define SM_LB     38208    // 2304
#define SM_GPART  40512    // 16*768 = 12288
#define SM_XTS    52800    // 96
#define SM_VTR4   52896    // 384
#define SM_VTRF   53280    // 96
#define SM_XW     53376    // 32
#define SM_BQ     53408    // 32
#define SM_B2S    53440    // 96
#define SM_RED    53536    // 32
#define STEP_SMEM_FLOATS 53568
#define STEP_SMEM_BYTES (STEP_SMEM_FLOATS * 4)   // 214,272 B

// ---------------- device scratch (allocation-free rule) ----------------
__device__ float g_C2[(size_t)8 * 9216 * 64];                  // 18.9MB (for z0)
__device__ float g_cconst[64];
__device__ float g_relsum0[9216];
__device__ float g_z0[64];
__device__ float g_zbuf[(size_t)2048 * 64];
__device__ __nv_bfloat16 g_Ahi[(size_t)2048 * RELK];           // 302MB
__device__ __nv_bfloat16 g_Alo[(size_t)2048 * RELK];           // 302MB
__device__ __nv_bfloat16 g_Bhi[(size_t)64 * RELK];             // 9.4MB  [o][k]
__device__ __nv_bfloat16 g_Blo[(size_t)64 * RELK];             // 9.4MB

// ---------------- f32x2 packed helpers ----------------
__device__ __forceinline__ ull pk2(float x, float y) {
    ull r;
    asm("mov.b64 %0, {%1, %2};" : "=l"(r) : "f"(x), "f"(y));
    return r;
}
__device__ __forceinline__ void fma2(ull& d, ull a, ull b) {
    asm("fma.rn.f32x2 %0, %1, %2, %0;" : "+l"(d) : "l"(a), "l"(b));
}
__device__ __forceinline__ void add2(ull& d, ull a) {
    asm("add.rn.f32x2 %0, %0, %1;" : "+l"(d) : "l"(a));
}
__device__ __forceinline__ void upk2(float& lo, float& hi, ull v) {
    asm("mov.b64 {%0, %1}, %2;" : "=f"(lo), "=f"(hi) : "l"(v));
}
__device__ __forceinline__ uint32_t smem_u32(const void* p) {
    uint32_t a;
    asm("{ .reg .u64 t; cvta.to.shared.u64 t, %1; cvt.u32.u64 %0, t; }"
        : "=r"(a) : "l"(p));
    return a;
}

// ---- combined init (launch #1) ----
__global__ void init_kernel(const float* __restrict__ rb) {
    int idx = blockIdx.x * 256 + threadIdx.x;   // grid 512
    if (idx < 9216) {
        float s = 0.f;
#pragma unroll
        for (int n = 0; n < 8; ++n) s += rb[n * 9216 + idx];
        g_relsum0[idx] = s;
    }
    g_zbuf[idx] = 0.f;
    if (idx < 64) g_z0[idx] = 0.f;
}

// ---- C2 build + transposed bf16 hi/lo (launch #3) ----
__global__ void __launch_bounds__(256, 1) c2_kernel(const float* __restrict__ Wr,
                                                    const float* __restrict__ W3) {
    __shared__ float Wrs[32 * 96];
    __shared__ float W3s[96 * 64];
    __shared__ float smt[32][65];
    const int tid = threadIdx.x;
    const int de0 = blockIdx.x * 32;   // 288 de-tiles
    const int n = blockIdx.y;          // 8
    for (int p = tid; p < 3072; p += 256) Wrs[p] = Wr[de0 * 96 + p];
    for (int p = tid; p < 6144; p += 256) W3s[p] = W3[n * 6144 + p];
    __syncthreads();
    const int o = tid & 63, de_b = tid >> 6;
    float acc[8];
#pragma unroll
    for (int i = 0; i < 8; ++i) acc[i] = 0.f;
    for (int r = 0; r < 96; ++r) {
        float bv = W3s[r * 64 + o];
#pragma unroll
        for (int i = 0; i < 8; ++i)
            acc[i] = fmaf(Wrs[(de_b + 4 * i) * 96 + r], bv, acc[i]);
    }
#pragma unroll
    for (int i = 0; i < 8; ++i) {
        int de = de0 + de_b + 4 * i;
        g_C2[((size_t)n * 9216 + de) * 64 + o] = acc[i];
        smt[de_b + 4 * i][o] = acc[i];
    }
    __syncthreads();
    // transposed bf16 hi/lo: row o, k = n*9216 + de
    {
        const int o2 = tid >> 2, seg = tid & 3;
        float v[8];
#pragma unroll
        for (int r = 0; r < 8; ++r) v[r] = smt[seg * 8 + r][o2];
        uint32_t hw[4], lw[4];
#pragma unroll
        for (int p = 0; p < 4; ++p) {
            __nv_bfloat162 h = __floats2bfloat162_rn(v[2 * p], v[2 * p + 1]);
            float2 hf = __bfloat1622float2(h);
            __nv_bfloat162 l = __floats2bfloat162_rn(v[2 * p] - hf.x,
                                                     v[2 * p + 1] - hf.y);
            hw[p] = *(uint32_t*)&h;
            lw[p] = *(uint32_t*)&l;
        }
        size_t base = (size_t)o2 * RELK + (size_t)n * 9216 + de0 + seg * 8;
        *(uint4*)&g_Bhi[base] = make_uint4(hw[0], hw[1], hw[2], hw[3]);
        *(uint4*)&g_Blo[base] = make_uint4(lw[0], lw[1], lw[2], lw[3]);
    }
}

__global__ void cconst_kernel(const float* __restrict__ br,
                              const float* __restrict__ W3,
                              const float* __restrict__ b3) {
    int o = threadIdx.x;
    float acc = b3[o];
    for (int nr = 0; nr < 768; ++nr)
        acc = fmaf(br[nr % 96], W3[nr * 64 + o], acc);
    g_cconst[o] = acc;
}

__global__ void __launch_bounds__(256, 1) z0_kernel(const float* __restrict__ rb) {
    __shared__ float part[256];
    const int o = threadIdx.x & 63, kk = threadIdx.x >> 6;
    const size_t kbase = (size_t)blockIdx.x * 1152;
    float acc = 0.f;
    for (int k = kk; k < 1152; k += 4) {
        size_t kg = kbase + k;
        acc = fmaf(rb[kg], g_C2[kg * 64 + o], acc);
    }
    part[threadIdx.x] = acc;
    __syncthreads();
    if (threadIdx.x < 64) {
        float s = part[o] + part[64 + o] + part[128 + o] + part[192 + o];
        atomicAdd(&g_z0[o], s);
    }
}

// ---------------- phase 1: recurrent kernel (measured; op8 emits bf16) -------
__global__ void __launch_bounds__(384, 1) step_kernel(
    const float* __restrict__ x, const float* __restrict__ Wqkv,
    const float* __restrict__ bqkv, const float* __restrict__ ln_g,
    const float* __restrict__ ln_b, const float* __restrict__ pa1,
    const float* __restrict__ pa2, const float* __restrict__ pa3,
    const float* __restrict__ W2, const float* __restrict__ b2,
    const float* __restrict__ item_bias)
{
    extern __shared__ float sm[];
    float* Mi     = sm + SM_MI;
    float* relsum = sm + SM_RELSUM;
    ull*   tdup   = (ull*)(sm + SM_TDUP);
    float* qkvT   = sm + SM_QKVT;
    float* WqT    = sm + SM_WQT;
    float* lg     = sm + SM_LG;
    float* lb     = sm + SM_LB;
    float* Gpart  = sm + SM_GPART;
    float* xts    = sm + SM_XTS;
    float* vtr4   = sm + SM_VTR4;
    float* vtrF   = sm + SM_VTRF;
    float* xw     = sm + SM_XW;
    float* bq     = sm + SM_BQ;
    float* b2s    = sm + SM_B2S;
    float* red    = sm + SM_RED;

    const int tid = threadIdx.x;
    const int b = blockIdx.x;
    const float a1v = *pa1, a2v = *pa2, a3v = *pa3;

    for (int idx = tid; idx < 2304; idx += 384) {
        int f = idx / 24, h = idx % 24;
        WqT[h * 100 + f] = Wqkv[idx];
        lg[idx] = ln_g[idx];
        lb[idx] = ln_b[idx];
    }
    if (tid < 24) bq[tid] = bqkv[tid];
    if (tid < 96) b2s[tid] = b2[tid];
    for (int idx = tid; idx < 9216; idx += 384) {
        Mi[(idx / 96) * 100 + (idx % 96)] = item_bias[idx];
        relsum[idx] = g_relsum0[idx];
    }
    __syncthreads();

    for (int t = 0; t < 16; ++t) {
        if (tid < 96) xts[tid] = x[(t * 128 + b) * 96 + tid];
        __syncthreads();

        for (int idx = tid; idx < 9216; idx += 384) {
            int d = idx / 96, f = idx % 96;
            Mi[d * 100 + f] = fmaf(xts[d], xts[f], Mi[d * 100 + f]);
        }
        __syncthreads();

        {
            int f = tid % 96, q = tid / 96;
            int d0 = q * 24;
            float acc = 0.f;
#pragma unroll 6
            for (int d = d0; d < d0 + 24; ++d)
                acc = fmaf(Mi[d * 100 + f], relsum[d * 96 + f], acc);
            vtr4[q * 96 + f] = acc;
        }
        if (tid < 24) {
            float acc = 0.f;
            for (int f = 0; f < 96; ++f)
                acc = fmaf(xts[f], WqT[tid * 100 + f], acc);
            xw[tid] = acc;
        }
        __syncthreads();
        if (tid < 96)
            vtrF[tid] = vtr4[tid] + vtr4[96 + tid] + vtr4[192 + tid] + vtr4[288 + tid];
        __syncthreads();

        float s1 = 0.f, s2 = 0.f;
        {
            const int hg = tid / 96;
            const int d  = tid % 96;
            const int h0 = hg * 6;
            ull acc[6][2];
#pragma unroll
            for (int i = 0; i < 6; ++i) { acc[i][0] = 0ull; acc[i][1] = 0ull; }
#pragma unroll 6
            for (int fq = 0; fq < 24; ++fq) {
                ulonglong2 m2 = *(const ulonglong2*)&Mi[d * 100 + 4 * fq];
#pragma unroll
                for (int hh = 0; hh < 6; ++hh) {
                    ulonglong2 w2v = *(const ulonglong2*)&WqT[(h0 + hh) * 100 + 4 * fq];
                    fma2(acc[hh][0], m2.x, w2v.x);
                    fma2(acc[hh][1], m2.y, w2v.y);
                }
            }
            const float vtrd = vtrF[d];
#pragma unroll
            for (int hh = 0; hh < 6; ++hh) {
                float l0, h0f, l1, h1f;
                upk2(l0, h0f, acc[hh][0]);
                upk2(l1, h1f, acc[hh][1]);
                int h = h0 + hh;
                float v = (l0 + h0f) + (l1 + h1f) + bq[h] + a2v * vtrd * xw[h];
                qkvT[h * 100 + d] = v;
                s1 += v;
                s2 = fmaf(v, v, s2);
            }
        }
#pragma unroll
        for (int o = 16; o > 0; o >>= 1) {
            s1 += __shfl_down_sync(0xffffffffu, s1, o);
            s2 += __shfl_down_sync(0xffffffffu, s2, o);
        }
        if ((tid & 31) == 0) { red[(tid >> 5) * 2] = s1; red[(tid >> 5) * 2 + 1] = s2; }
        __syncthreads();
        if (tid == 0) {
            float S = 0.f, SS = 0.f;
            for (int w = 0; w < 12; ++w) { S += red[w * 2]; SS += red[w * 2 + 1]; }
            float mu = S * (1.f / 2304.f);
            float var = SS * (1.f / 2304.f) - mu * mu;
            red[30] = mu;
            red[31] = rsqrtf(var + 1e-5f);
        }
        __syncthreads();
        const float mu = red[30], rstd = red[31];

        for (int idx = tid; idx < 2304; idx += 384) {
            int h = idx / 96, d = idx % 96;
            float v = qkvT[h * 100 + d];
            qkvT[h * 100 + d] = (v - mu) * rstd * lg[d * 24 + h] + lb[d * 24 + h];
        }
        __syncthreads();

        for (int idx = tid; idx < 6144; idx += 384) {
            int j = idx & 7, d = (idx >> 3) % 96, n = idx / 768;
            float p = qkvT[n * 100 + d] * qkvT[(8 + j) * 100 + d];
            float e = __expf(2.f * p);
            float tv = 1.f - 2.f / (e + 1.f);
            tdup[idx] = pk2(tv, tv);
        }
        __syncthreads();

        {
            const int fp2 = tid % 24;
            const int g   = tid / 24;
            const int f0  = 4 * fp2;
            ull acc[8][2];
#pragma unroll
            for (int j = 0; j < 8; ++j) { acc[j][0] = 0ull; acc[j][1] = 0ull; }
            const float* w2p = W2 + (size_t)(g * 48) * 96 + f0;
            const ulonglong2* tp = (const ulonglong2*)&tdup[(g * 48) * 8];
#pragma unroll 4
            for (int m = 0; m < 48; ++m) {
                float4 wv = *(const float4*)&w2p[(size_t)m * 96];
                ull w01 = pk2(wv.x, wv.y);
                ull w23 = pk2(wv.z, wv.w);
                ulonglong2 t01 = tp[m * 4 + 0];
                ulonglong2 t23 = tp[m * 4 + 1];
                ulonglong2 t45 = tp[m * 4 + 2];
                ulonglong2 t67 = tp[m * 4 + 3];
                fma2(acc[0][0], t01.x, w01); fma2(acc[0][1], t01.x, w23);
                fma2(acc[1][0], t01.y, w01); fma2(acc[1][1], t01.y, w23);
                fma2(acc[2][0], t23.x, w01); fma2(acc[2][1], t23.x, w23);
                fma2(acc[3][0], t23.y, w01); fma2(acc[3][1], t23.y, w23);
                fma2(acc[4][0], t45.x, w01); fma2(acc[4][1], t45.x, w23);
                fma2(acc[5][0], t45.y, w01); fma2(acc[5][1], t45.y, w23);
                fma2(acc[6][0], t67.x, w01); fma2(acc[6][1], t67.x, w23);
                fma2(acc[7][0], t67.y, w01); fma2(acc[7][1], t67.y, w23);
            }
#pragma unroll
            for (int j = 0; j < 8; ++j)
                *(ulonglong2*)&Gpart[g * 768 + j * 96 + f0] =
                    make_ulonglong2(acc[j][0], acc[j][1]);
        }
        __syncthreads();
        for (int idx = tid; idx < 768; idx += 384) {
            float s = Gpart[idx];
#pragma unroll
            for (int g2 = 1; g2 < 16; ++g2) s += Gpart[g2 * 768 + idx];
            Gpart[idx] = s;
        }
        __syncthreads();

        {
            const int e = tid >> 2, part = tid & 3;
            const int f0b = part * 24;
            ull vp[8];
#pragma unroll
            for (int j = 0; j < 8; ++j) {
                float ve = qkvT[(16 + j) * 100 + e];
                vp[j] = pk2(ve, ve);
            }
#pragma unroll 3
            for (int q = 0; q < 12; ++q) {
                int f0 = f0b + q * 2;
                ull acc = 0ull;
#pragma unroll
                for (int j = 0; j < 8; ++j)
                    fma2(acc, vp[j], *(const ull*)&Gpart[j * 96 + f0]);
                float lo, hi;
                upk2(lo, hi, acc);
                Mi[e * 100 + f0]     = fmaf(a3v, lo + b2s[f0],     Mi[e * 100 + f0]);
                Mi[e * 100 + f0 + 1] = fmaf(a3v, hi + b2s[f0 + 1], Mi[e * 100 + f0 + 1]);
            }
        }

        // op8: R0 -> bf16 hi/lo; relsum = a1*relsum + sum_n R0
        {
            const int ep = tid % 24;
            const int g  = tid / 24;
            const int e0 = 4 * ep;
            ull vP[8][2];
#pragma unroll
            for (int j = 0; j < 8; ++j) {
                ulonglong2 tv = *(const ulonglong2*)&qkvT[(16 + j) * 100 + e0];
                vP[j][0] = tv.x;
                vP[j][1] = tv.y;
            }
            const size_t mrow = (size_t)(t * 128 + b) * RELK;
            ull racc[6][2];
#pragma unroll
            for (int mm = 0; mm < 6; ++mm) { racc[mm][0] = 0ull; racc[mm][1] = 0ull; }
#pragma unroll 4
            for (int it = g; it < 768; it += 16) {
                const ulonglong2* tp = (const ulonglong2*)&tdup[it * 8];
                ulonglong2 t01 = tp[0], t23 = tp[1], t45 = tp[2], t67 = tp[3];
                ull a0 = 0ull, a1_ = 0ull;
                fma2(a0, t01.x, vP[0][0]); fma2(a1_, t01.x, vP[0][1]);
                fma2(a0, t01.y, vP[1][0]); fma2(a1_, t01.y, vP[1][1]);
                fma2(a0, t23.x, vP[2][0]); fma2(a1_, t23.x, vP[2][1]);
                fma2(a0, t23.y, vP[3][0]); fma2(a1_, t23.y, vP[3][1]);
                fma2(a0, t45.x, vP[4][0]); fma2(a1_, t45.x, vP[4][1]);
                fma2(a0, t45.y, vP[5][0]); fma2(a1_, t45.y, vP[5][1]);
                fma2(a0, t67.x, vP[6][0]); fma2(a1_, t67.x, vP[6][1]);
                fma2(a0, t67.y, vP[7][0]); fma2(a1_, t67.y, vP[7][1]);
                float f0, f1, f2, f3;
                upk2(f0, f1, a0);
                upk2(f2, f3, a1_);
                __nv_bfloat162 h01 = __floats2bfloat162_rn(f0, f1);
                __nv_bfloat162 h23 = __floats2bfloat162_rn(f2, f3);
                float2 hf01 = __bfloat1622float2(h01);
                float2 hf23 = __bfloat1622float2(h23);
                __nv_bfloat162 l01 = __floats2bfloat162_rn(f0 - hf01.x, f1 - hf01.y);
                __nv_bfloat162 l23 = __floats2bfloat162_rn(f2 - hf23.x, f3 - hf23.y);
                uint32_t uh0 = *(uint32_t*)&h01, uh1 = *(uint32_t*)&h23;
                uint32_t ul0 = *(uint32_t*)&l01, ul1 = *(uint32_t*)&l23;
                *(ull*)&g_Ahi[mrow + (size_t)it * 96 + e0] = ((ull)uh1 << 32) | uh0;
                *(ull*)&g_Alo[mrow + (size_t)it * 96 + e0] = ((ull)ul1 << 32) | ul0;
                int mm = (it >> 4) % 6;
                add2(racc[mm][0], a0);
                add2(racc[mm][1], a1_);
            }
            const ull a1P = pk2(a1v, a1v);
#pragma unroll
            for (int mm = 0; mm < 6; ++mm) {
                int d = g + 16 * mm;
                ulonglong2 old = *(const ulonglong2*)&relsum[d * 96 + e0];
                fma2(racc[mm][0], a1P, old.x);
                fma2(racc[mm][1], a1P, old.y);
                *(ulonglong2*)&relsum[d * 96 + e0] =
                    make_ulonglong2(racc[mm][0], racc[mm][1]);
            }
        }
        __syncthreads();
    }
}

// ---------------- phase 2: HMMA bf16 GEMM via mma.sync (launch #4) -----------
// zbuf[m,o] += sum_k A[m,k]*B[o,k], 3-term bf16 split, fp32 register accum.
// grid (16 m-tiles of 128, 24 k-splits of 3072), 256 thr = 8 warps x m16 x n64.
#define HG_A_HI 0
#define HG_A_LO 16384
#define HG_B_HI 32768
#define HG_B_LO 40960
#define HG_SMEM 49152

__device__ __forceinline__ void ldsm4(uint32_t* f, uint32_t addr) {
    asm volatile("ldmatrix.sync.aligned.m8n8.x4.shared.b16 {%0,%1,%2,%3}, [%4];"
                 : "=r"(f[0]), "=r"(f[1]), "=r"(f[2]), "=r"(f[3]) : "r"(addr));
}
__device__ __forceinline__ void mma16816(float* c, const uint32_t* a,
                                         uint32_t b0, uint32_t b1) {
    asm volatile(
        "mma.sync.aligned.m16n8k16.row.col.f32.bf16.bf16.f32 "
        "{%0,%1,%2,%3}, {%4,%5,%6,%7}, {%8,%9}, {%0,%1,%2,%3};"
        : "+f"(c[0]), "+f"(c[1]), "+f"(c[2]), "+f"(c[3])
        : "r"(a[0]), "r"(a[1]), "r"(a[2]), "r"(a[3]), "r"(b0), "r"(b1));
}

__global__ void __launch_bounds__(256) hmma_gemm_kernel() {
    extern __shared__ char smc[];
    const uint32_t sbase = smem_u32(smc);
    const int tid = threadIdx.x;
    const int wid = tid >> 5, lane = tid & 31;
    const int m0 = blockIdx.x * 128;
    const size_t k0 = (size_t)blockIdx.y * 3072;
    const int rit = lane & 7, ti = lane >> 3;

    float acc[8][4];
#pragma unroll
    for (int i = 0; i < 8; ++i)
#pragma unroll
        for (int j = 0; j < 4; ++j) acc[i][j] = 0.f;

    for (int ch = 0; ch < 48; ++ch) {
        const size_t kc = k0 + (size_t)ch * 64;
        // A tiles: 128 rows x 64 k (128B/row), xor-16B swizzle
#pragma unroll
        for (int it = 0; it < 4; ++it) {
            int idx = it * 256 + tid;
            int r = idx >> 3, q = idx & 7;
            size_t goff = (size_t)(m0 + r) * RELK + kc + q * 8;
            uint4 vh = *(const uint4*)&g_Ahi[goff];
            uint4 vl = *(const uint4*)&g_Alo[goff];
            uint32_t so = (uint32_t)(r * 128 + ((q ^ (r & 7)) << 4));
            *(uint4*)(smc + HG_A_HI + so) = vh;
            *(uint4*)(smc + HG_A_LO + so) = vl;
        }
        // B tiles: 64 rows (o) x 64 k
#pragma unroll
        for (int it = 0; it < 2; ++it) {
            int idx = it * 256 + tid;
            int r = idx >> 3, q = idx & 7;
            size_t goff = (size_t)r * RELK + kc + q * 8;
            uint4 vh = *(const uint4*)&g_Bhi[goff];
            uint4 vl = *(const uint4*)&g_Blo[goff];
            uint32_t so = (uint32_t)(r * 128 + ((q ^ (r & 7)) << 4));
            *(uint4*)(smc + HG_B_HI + so) = vh;
            *(uint4*)(smc + HG_B_LO + so) = vl;
        }
        __syncthreads();

#pragma unroll
        for (int ks = 0; ks < 4; ++ks) {
            // A fragments (m16k16): tiles {m0-7 k0-7, m8-15 k0-7, m0-7 k8-15, m8-15 k8-15}
            uint32_t ahi[4], alo[4];
            {
                int r  = (wid << 4) + ((ti & 1) << 3) + rit;
                int kb = 2 * ks + (ti >> 1);
                uint32_t so = (uint32_t)(r * 128 + ((kb ^ (r & 7)) << 4));
                ldsm4(ahi, sbase + HG_A_HI + so);
                ldsm4(alo, sbase + HG_A_LO + so);
            }
#pragma unroll
            for (int nt2 = 0; nt2 < 4; ++nt2) {
                // B fragments: tiles {n0-7 k0-7, n0-7 k8-15, n8-15 k0-7, n8-15 k8-15}
                uint32_t bhi[4], blo[4];
                int n  = (nt2 << 4) + ((ti >> 1) << 3) + rit;
                int kb = 2 * ks + (ti & 1);
                uint32_t so = (uint32_t)(n * 128 + ((kb ^ (n & 7)) << 4));
                ldsm4(bhi, sbase + HG_B_HI + so);
                ldsm4(blo, sbase + HG_B_LO + so);
                // n-tile 2*nt2
                mma16816(acc[2 * nt2], ahi, bhi[0], bhi[1]);
                mma16816(acc[2 * nt2], ahi, blo[0], blo[1]);
                mma16816(acc[2 * nt2], alo, bhi[0], bhi[1]);
                // n-tile 2*nt2+1
                mma16816(acc[2 * nt2 + 1], ahi, bhi[2], bhi[3]);
                mma16816(acc[2 * nt2 + 1], ahi, blo[2], blo[3]);
                mma16816(acc[2 * nt2 + 1], alo, bhi[2], bhi[3]);
            }
        }
        __syncthreads();
    }

    // epilogue: C frag (m16n8): c0=(grp,2t), c1=(grp,2t+1), c2=(grp+8,2t), c3=(grp+8,2t+1)
    const int grp = lane >> 2, tig = lane & 3;
    const int m = m0 + wid * 16 + grp;
#pragma unroll
    for (int nt = 0; nt < 8; ++nt) {
        int o = nt * 8 + 2 * tig;
        atomicAdd(&g_zbuf[(size_t)m * 64 + o],           acc[nt][0]);
        atomicAdd(&g_zbuf[(size_t)m * 64 + o + 1],       acc[nt][1]);
        atomicAdd(&g_zbuf[(size_t)(m + 8) * 64 + o],     acc[nt][2]);
        atomicAdd(&g_zbuf[(size_t)(m + 8) * 64 + o + 1], acc[nt][3]);
    }
}

__global__ void scan_kernel(float* __restrict__ out, const float* __restrict__ pa1) {
    const int b = blockIdx.x;
    const int o = threadIdx.x;
    const float a1v = *pa1;
    const float z0o = g_z0[o], cc = g_cconst[o];
    float acc = 0.f, p = 1.f;
#pragma unroll
    for (int t = 0; t < 16; ++t) {
        p *= a1v;
        acc = fmaf(a1v, acc, g_zbuf[(size_t)(t * 128 + b) * 64 + o]);
        out[(size_t)(t * 128 + b) * 64 + o] = fmaf(p, z0o, acc + cc);
    }
}

extern "C" void kernel_launch(void* const* d_in, const int* in_sizes, int n_in,
                              void* d_out, int out_size) {
    const float* x         = (const float*)d_in[0];
    const float* Wqkv      = (const float*)d_in[1];
    const float* bqkv      = (const float*)d_in[2];
    const float* ln_g      = (const float*)d_in[3];
    const float* ln_b      = (const float*)d_in[4];
    const float* a1        = (const float*)d_in[5];
    const float* a2        = (const float*)d_in[6];
    const float* a3        = (const float*)d_in[7];
    const float* W2        = (const float*)d_in[8];
    const float* b2        = (const float*)d_in[9];
    const float* Wr        = (const float*)d_in[10];
    const float* br        = (const float*)d_in[11];
    const float* W3        = (const float*)d_in[12];
    const float* b3        = (const float*)d_in[13];
    const float* item_bias = (const float*)d_in[14];
    const float* rel_bias  = (const float*)d_in[15];
    float* out = (float*)d_out;

    cudaFuncSetAttribute(step_kernel, cudaFuncAttributeMaxDynamicSharedMemorySize,
                         STEP_SMEM_BYTES);
    cudaFuncSetAttribute(hmma_gemm_kernel, cudaFuncAttributeMaxDynamicSharedMemorySize,
                         HG_SMEM);

    init_kernel<<<512, 256>>>(rel_bias);                                        // 1
    step_kernel<<<128, 384, STEP_SMEM_BYTES>>>(x, Wqkv, bqkv, ln_g, ln_b,
                                               a1, a2, a3, W2, b2, item_bias);  // 2
    c2_kernel<<<dim3(288, 8), 256>>>(Wr, W3);                                   // 3
    hmma_gemm_kernel<<<dim3(16, 24), 256, HG_SMEM>>>();                         // 4 (profiled)
    z0_kernel<<<64, 256>>>(rel_bias);                                           // 5
    cconst_kernel<<<1, 64>>>(br, W3, b3);                                       // 6
    scan_kernel<<<128, 64>>>(out, a1);                                          // 7
}

// round 14
// speedup vs baseline: 1.9274x; 1.2164x over previous
#include <cuda_runtime.h>
#include <cuda_bf16.h>
#include <cstdint>

typedef unsigned long long ull;

#define RELK 73728

// ---------------- smem layout for step_kernel (float offsets) ----------------
#define SM_MI     0        // 96*100
#define SM_RELSUM 9600     // 9216
#define SM_TDUP   18816    // 12288 floats = 6144 ull
#define SM_QKVT   31104    // 24*100
#define SM_WQT    33504    // 24*100
#define SM_LG     35904    // 2304
#define SM_LB     38208    // 2304
#define SM_GPART  40512    // 16*768 = 12288
#define SM_XTS    52800    // 96
#define SM_VTR4   52896    // 384
#define SM_VTRF   53280    // 96
#define SM_XW     53376    // 32
#define SM_BQ     53408    // 32
#define SM_B2S    53440    // 96
#define SM_RED    53536    // 32
#define STEP_SMEM_FLOATS 53568
#define STEP_SMEM_BYTES (STEP_SMEM_FLOATS * 4)   // 214,272 B

// ---------------- device scratch (allocation-free rule) ----------------
__device__ float g_C2[(size_t)8 * 9216 * 64];                  // 18.9MB (for z0)
__device__ float g_cconst[64];
__device__ float g_relsum0[9216];
__device__ float g_z0[64];
__device__ float g_zbuf[(size_t)2048 * 64];
__device__ __nv_bfloat16 g_Ahi[(size_t)2048 * RELK];           // 302MB
__device__ __nv_bfloat16 g_Alo[(size_t)2048 * RELK];           // 302MB
__device__ __nv_bfloat16 g_Bhi[(size_t)64 * RELK];             // 9.4MB  [o][k]
__device__ __nv_bfloat16 g_Blo[(size_t)64 * RELK];             // 9.4MB

// ---------------- f32x2 packed helpers ----------------
__device__ __forceinline__ ull pk2(float x, float y) {
    ull r;
    asm("mov.b64 %0, {%1, %2};" : "=l"(r) : "f"(x), "f"(y));
    return r;
}
__device__ __forceinline__ void fma2(ull& d, ull a, ull b) {
    asm("fma.rn.f32x2 %0, %1, %2, %0;" : "+l"(d) : "l"(a), "l"(b));
}
__device__ __forceinline__ void add2(ull& d, ull a) {
    asm("add.rn.f32x2 %0, %0, %1;" : "+l"(d) : "l"(a));
}
__device__ __forceinline__ void upk2(float& lo, float& hi, ull v) {
    asm("mov.b64 {%0, %1}, %2;" : "=f"(lo), "=f"(hi) : "l"(v));
}
__device__ __forceinline__ uint32_t smem_u32(const void* p) {
    uint32_t a;
    asm("{ .reg .u64 t; cvta.to.shared.u64 t, %1; cvt.u32.u64 %0, t; }"
        : "=r"(a) : "l"(p));
    return a;
}
__device__ __forceinline__ void cpa16(uint32_t dst, const void* src) {
    asm volatile("cp.async.cg.shared.global [%0], [%1], 16;"
                 :: "r"(dst), "l"(__cvta_generic_to_global(src)) : "memory");
}

// ---- combined init (launch #1) ----
__global__ void init_kernel(const float* __restrict__ rb) {
    int idx = blockIdx.x * 256 + threadIdx.x;   // grid 512
    if (idx < 9216) {
        float s = 0.f;
#pragma unroll
        for (int n = 0; n < 8; ++n) s += rb[n * 9216 + idx];
        g_relsum0[idx] = s;
    }
    g_zbuf[idx] = 0.f;
    if (idx < 64) g_z0[idx] = 0.f;
}

// ---- C2 build + transposed bf16 hi/lo (launch #3) ----
__global__ void __launch_bounds__(256, 1) c2_kernel(const float* __restrict__ Wr,
                                                    const float* __restrict__ W3) {
    __shared__ float Wrs[32 * 96];
    __shared__ float W3s[96 * 64];
    __shared__ float smt[32][65];
    const int tid = threadIdx.x;
    const int de0 = blockIdx.x * 32;   // 288 de-tiles
    const int n = blockIdx.y;          // 8
    for (int p = tid; p < 3072; p += 256) Wrs[p] = Wr[de0 * 96 + p];
    for (int p = tid; p < 6144; p += 256) W3s[p] = W3[n * 6144 + p];
    __syncthreads();
    const int o = tid & 63, de_b = tid >> 6;
    float acc[8];
#pragma unroll
    for (int i = 0; i < 8; ++i) acc[i] = 0.f;
    for (int r = 0; r < 96; ++r) {
        float bv = W3s[r * 64 + o];
#pragma unroll
        for (int i = 0; i < 8; ++i)
            acc[i] = fmaf(Wrs[(de_b + 4 * i) * 96 + r], bv, acc[i]);
    }
#pragma unroll
    for (int i = 0; i < 8; ++i) {
        int de = de0 + de_b + 4 * i;
        g_C2[((size_t)n * 9216 + de) * 64 + o] = acc[i];
        smt[de_b + 4 * i][o] = acc[i];
    }
    __syncthreads();
    // transposed bf16 hi/lo: row o, k = n*9216 + de
    {
        const int o2 = tid >> 2, seg = tid & 3;
        float v[8];
#pragma unroll
        for (int r = 0; r < 8; ++r) v[r] = smt[seg * 8 + r][o2];
        uint32_t hw[4], lw[4];
#pragma unroll
        for (int p = 0; p < 4; ++p) {
            __nv_bfloat162 h = __floats2bfloat162_rn(v[2 * p], v[2 * p + 1]);
            float2 hf = __bfloat1622float2(h);
            __nv_bfloat162 l = __floats2bfloat162_rn(v[2 * p] - hf.x,
                                                     v[2 * p + 1] - hf.y);
            hw[p] = *(uint32_t*)&h;
            lw[p] = *(uint32_t*)&l;
        }
        size_t base = (size_t)o2 * RELK + (size_t)n * 9216 + de0 + seg * 8;
        *(uint4*)&g_Bhi[base] = make_uint4(hw[0], hw[1], hw[2], hw[3]);
        *(uint4*)&g_Blo[base] = make_uint4(lw[0], lw[1], lw[2], lw[3]);
    }
}

__global__ void cconst_kernel(const float* __restrict__ br,
                              const float* __restrict__ W3,
                              const float* __restrict__ b3) {
    int o = threadIdx.x;
    float acc = b3[o];
    for (int nr = 0; nr < 768; ++nr)
        acc = fmaf(br[nr % 96], W3[nr * 64 + o], acc);
    g_cconst[o] = acc;
}

__global__ void __launch_bounds__(256, 1) z0_kernel(const float* __restrict__ rb) {
    __shared__ float part[256];
    const int o = threadIdx.x & 63, kk = threadIdx.x >> 6;
    const size_t kbase = (size_t)blockIdx.x * 1152;
    float acc = 0.f;
    for (int k = kk; k < 1152; k += 4) {
        size_t kg = kbase + k;
        acc = fmaf(rb[kg], g_C2[kg * 64 + o], acc);
    }
    part[threadIdx.x] = acc;
    __syncthreads();
    if (threadIdx.x < 64) {
        float s = part[o] + part[64 + o] + part[128 + o] + part[192 + o];
        atomicAdd(&g_z0[o], s);
    }
}

// ---------------- phase 1: recurrent kernel (measured; op8 emits bf16) -------
__global__ void __launch_bounds__(384, 1) step_kernel(
    const float* __restrict__ x, const float* __restrict__ Wqkv,
    const float* __restrict__ bqkv, const float* __restrict__ ln_g,
    const float* __restrict__ ln_b, const float* __restrict__ pa1,
    const float* __restrict__ pa2, const float* __restrict__ pa3,
    const float* __restrict__ W2, const float* __restrict__ b2,
    const float* __restrict__ item_bias)
{
    extern __shared__ float sm[];
    float* Mi     = sm + SM_MI;
    float* relsum = sm + SM_RELSUM;
    ull*   tdup   = (ull*)(sm + SM_TDUP);
    float* qkvT   = sm + SM_QKVT;
    float* WqT    = sm + SM_WQT;
    float* lg     = sm + SM_LG;
    float* lb     = sm + SM_LB;
    float* Gpart  = sm + SM_GPART;
    float* xts    = sm + SM_XTS;
    float* vtr4   = sm + SM_VTR4;
    float* vtrF   = sm + SM_VTRF;
    float* xw     = sm + SM_XW;
    float* bq     = sm + SM_BQ;
    float* b2s    = sm + SM_B2S;
    float* red    = sm + SM_RED;

    const int tid = threadIdx.x;
    const int b = blockIdx.x;
    const float a1v = *pa1, a2v = *pa2, a3v = *pa3;

    for (int idx = tid; idx < 2304; idx += 384) {
        int f = idx / 24, h = idx % 24;
        WqT[h * 100 + f] = Wqkv[idx];
        lg[idx] = ln_g[idx];
        lb[idx] = ln_b[idx];
    }
    if (tid < 24) bq[tid] = bqkv[tid];
    if (tid < 96) b2s[tid] = b2[tid];
    for (int idx = tid; idx < 9216; idx += 384) {
        Mi[(idx / 96) * 100 + (idx % 96)] = item_bias[idx];
        relsum[idx] = g_relsum0[idx];
    }
    __syncthreads();

    for (int t = 0; t < 16; ++t) {
        if (tid < 96) xts[tid] = x[(t * 128 + b) * 96 + tid];
        __syncthreads();

        for (int idx = tid; idx < 9216; idx += 384) {
            int d = idx / 96, f = idx % 96;
            Mi[d * 100 + f] = fmaf(xts[d], xts[f], Mi[d * 100 + f]);
        }
        __syncthreads();

        {
            int f = tid % 96, q = tid / 96;
            int d0 = q * 24;
            float acc = 0.f;
#pragma unroll 6
            for (int d = d0; d < d0 + 24; ++d)
                acc = fmaf(Mi[d * 100 + f], relsum[d * 96 + f], acc);
            vtr4[q * 96 + f] = acc;
        }
        if (tid < 24) {
            float acc = 0.f;
            for (int f = 0; f < 96; ++f)
                acc = fmaf(xts[f], WqT[tid * 100 + f], acc);
            xw[tid] = acc;
        }
        __syncthreads();
        if (tid < 96)
            vtrF[tid] = vtr4[tid] + vtr4[96 + tid] + vtr4[192 + tid] + vtr4[288 + tid];
        __syncthreads();

        float s1 = 0.f, s2 = 0.f;
        {
            const int hg = tid / 96;
            const int d  = tid % 96;
            const int h0 = hg * 6;
            ull acc[6][2];
#pragma unroll
            for (int i = 0; i < 6; ++i) { acc[i][0] = 0ull; acc[i][1] = 0ull; }
#pragma unroll 6
            for (int fq = 0; fq < 24; ++fq) {
                ulonglong2 m2 = *(const ulonglong2*)&Mi[d * 100 + 4 * fq];
#pragma unroll
                for (int hh = 0; hh < 6; ++hh) {
                    ulonglong2 w2v = *(const ulonglong2*)&WqT[(h0 + hh) * 100 + 4 * fq];
                    fma2(acc[hh][0], m2.x, w2v.x);
                    fma2(acc[hh][1], m2.y, w2v.y);
                }
            }
            const float vtrd = vtrF[d];
#pragma unroll
            for (int hh = 0; hh < 6; ++hh) {
                float l0, h0f, l1, h1f;
                upk2(l0, h0f, acc[hh][0]);
                upk2(l1, h1f, acc[hh][1]);
                int h = h0 + hh;
                float v = (l0 + h0f) + (l1 + h1f) + bq[h] + a2v * vtrd * xw[h];
                qkvT[h * 100 + d] = v;
                s1 += v;
                s2 = fmaf(v, v, s2);
            }
        }
#pragma unroll
        for (int o = 16; o > 0; o >>= 1) {
            s1 += __shfl_down_sync(0xffffffffu, s1, o);
            s2 += __shfl_down_sync(0xffffffffu, s2, o);
        }
        if ((tid & 31) == 0) { red[(tid >> 5) * 2] = s1; red[(tid >> 5) * 2 + 1] = s2; }
        __syncthreads();
        if (tid == 0) {
            float S = 0.f, SS = 0.f;
            for (int w = 0; w < 12; ++w) { S += red[w * 2]; SS += red[w * 2 + 1]; }
            float mu = S * (1.f / 2304.f);
            float var = SS * (1.f / 2304.f) - mu * mu;
            red[30] = mu;
            red[31] = rsqrtf(var + 1e-5f);
        }
        __syncthreads();
        const float mu = red[30], rstd = red[31];

        for (int idx = tid; idx < 2304; idx += 384) {
            int h = idx / 96, d = idx % 96;
            float v = qkvT[h * 100 + d];
            qkvT[h * 100 + d] = (v - mu) * rstd * lg[d * 24 + h] + lb[d * 24 + h];
        }
        __syncthreads();

        for (int idx = tid; idx < 6144; idx += 384) {
            int j = idx & 7, d = (idx >> 3) % 96, n = idx / 768;
            float p = qkvT[n * 100 + d] * qkvT[(8 + j) * 100 + d];
            float e = __expf(2.f * p);
            float tv = 1.f - 2.f / (e + 1.f);
            tdup[idx] = pk2(tv, tv);
        }
        __syncthreads();

        {
            const int fp2 = tid % 24;
            const int g   = tid / 24;
            const int f0  = 4 * fp2;
            ull acc[8][2];
#pragma unroll
            for (int j = 0; j < 8; ++j) { acc[j][0] = 0ull; acc[j][1] = 0ull; }
            const float* w2p = W2 + (size_t)(g * 48) * 96 + f0;
            const ulonglong2* tp = (const ulonglong2*)&tdup[(g * 48) * 8];
#pragma unroll 4
            for (int m = 0; m < 48; ++m) {
                float4 wv = *(const float4*)&w2p[(size_t)m * 96];
                ull w01 = pk2(wv.x, wv.y);
                ull w23 = pk2(wv.z, wv.w);
                ulonglong2 t01 = tp[m * 4 + 0];
                ulonglong2 t23 = tp[m * 4 + 1];
                ulonglong2 t45 = tp[m * 4 + 2];
                ulonglong2 t67 = tp[m * 4 + 3];
                fma2(acc[0][0], t01.x, w01); fma2(acc[0][1], t01.x, w23);
                fma2(acc[1][0], t01.y, w01); fma2(acc[1][1], t01.y, w23);
                fma2(acc[2][0], t23.x, w01); fma2(acc[2][1], t23.x, w23);
                fma2(acc[3][0], t23.y, w01); fma2(acc[3][1], t23.y, w23);
                fma2(acc[4][0], t45.x, w01); fma2(acc[4][1], t45.x, w23);
                fma2(acc[5][0], t45.y, w01); fma2(acc[5][1], t45.y, w23);
                fma2(acc[6][0], t67.x, w01); fma2(acc[6][1], t67.x, w23);
                fma2(acc[7][0], t67.y, w01); fma2(acc[7][1], t67.y, w23);
            }
#pragma unroll
            for (int j = 0; j < 8; ++j)
                *(ulonglong2*)&Gpart[g * 768 + j * 96 + f0] =
                    make_ulonglong2(acc[j][0], acc[j][1]);
        }
        __syncthreads();
        for (int idx = tid; idx < 768; idx += 384) {
            float s = Gpart[idx];
#pragma unroll
            for (int g2 = 1; g2 < 16; ++g2) s += Gpart[g2 * 768 + idx];
            Gpart[idx] = s;
        }
        __syncthreads();

        {
            const int e = tid >> 2, part = tid & 3;
            const int f0b = part * 24;
            ull vp[8];
#pragma unroll
            for (int j = 0; j < 8; ++j) {
                float ve = qkvT[(16 + j) * 100 + e];
                vp[j] = pk2(ve, ve);
            }
#pragma unroll 3
            for (int q = 0; q < 12; ++q) {
                int f0 = f0b + q * 2;
                ull acc = 0ull;
#pragma unroll
                for (int j = 0; j < 8; ++j)
                    fma2(acc, vp[j], *(const ull*)&Gpart[j * 96 + f0]);
                float lo, hi;
                upk2(lo, hi, acc);
                Mi[e * 100 + f0]     = fmaf(a3v, lo + b2s[f0],     Mi[e * 100 + f0]);
                Mi[e * 100 + f0 + 1] = fmaf(a3v, hi + b2s[f0 + 1], Mi[e * 100 + f0 + 1]);
            }
        }

        // op8: R0 -> bf16 hi/lo; relsum = a1*relsum + sum_n R0
        {
            const int ep = tid % 24;
            const int g  = tid / 24;
            const int e0 = 4 * ep;
            ull vP[8][2];
#pragma unroll
            for (int j = 0; j < 8; ++j) {
                ulonglong2 tv = *(const ulonglong2*)&qkvT[(16 + j) * 100 + e0];
                vP[j][0] = tv.x;
                vP[j][1] = tv.y;
            }
            const size_t mrow = (size_t)(t * 128 + b) * RELK;
            ull racc[6][2];
#pragma unroll
            for (int mm = 0; mm < 6; ++mm) { racc[mm][0] = 0ull; racc[mm][1] = 0ull; }
#pragma unroll 4
            for (int it = g; it < 768; it += 16) {
                const ulonglong2* tp = (const ulonglong2*)&tdup[it * 8];
                ulonglong2 t01 = tp[0], t23 = tp[1], t45 = tp[2], t67 = tp[3];
                ull a0 = 0ull, a1_ = 0ull;
                fma2(a0, t01.x, vP[0][0]); fma2(a1_, t01.x, vP[0][1]);
                fma2(a0, t01.y, vP[1][0]); fma2(a1_, t01.y, vP[1][1]);
                fma2(a0, t23.x, vP[2][0]); fma2(a1_, t23.x, vP[2][1]);
                fma2(a0, t23.y, vP[3][0]); fma2(a1_, t23.y, vP[3][1]);
                fma2(a0, t45.x, vP[4][0]); fma2(a1_, t45.x, vP[4][1]);
                fma2(a0, t45.y, vP[5][0]); fma2(a1_, t45.y, vP[5][1]);
                fma2(a0, t67.x, vP[6][0]); fma2(a1_, t67.x, vP[6][1]);
                fma2(a0, t67.y, vP[7][0]); fma2(a1_, t67.y, vP[7][1]);
                float f0, f1, f2, f3;
                upk2(f0, f1, a0);
                upk2(f2, f3, a1_);
                __nv_bfloat162 h01 = __floats2bfloat162_rn(f0, f1);
                __nv_bfloat162 h23 = __floats2bfloat162_rn(f2, f3);
                float2 hf01 = __bfloat1622float2(h01);
                float2 hf23 = __bfloat1622float2(h23);
                __nv_bfloat162 l01 = __floats2bfloat162_rn(f0 - hf01.x, f1 - hf01.y);
                __nv_bfloat162 l23 = __floats2bfloat162_rn(f2 - hf23.x, f3 - hf23.y);
                uint32_t uh0 = *(uint32_t*)&h01, uh1 = *(uint32_t*)&h23;
                uint32_t ul0 = *(uint32_t*)&l01, ul1 = *(uint32_t*)&l23;
                *(ull*)&g_Ahi[mrow + (size_t)it * 96 + e0] = ((ull)uh1 << 32) | uh0;
                *(ull*)&g_Alo[mrow + (size_t)it * 96 + e0] = ((ull)ul1 << 32) | ul0;
                int mm = (it >> 4) % 6;
                add2(racc[mm][0], a0);
                add2(racc[mm][1], a1_);
            }
            const ull a1P = pk2(a1v, a1v);
#pragma unroll
            for (int mm = 0; mm < 6; ++mm) {
                int d = g + 16 * mm;
                ulonglong2 old = *(const ulonglong2*)&relsum[d * 96 + e0];
                fma2(racc[mm][0], a1P, old.x);
                fma2(racc[mm][1], a1P, old.y);
                *(ulonglong2*)&relsum[d * 96 + e0] =
                    make_ulonglong2(racc[mm][0], racc[mm][1]);
            }
        }
        __syncthreads();
    }
}

// ---------------- phase 2: HMMA bf16 GEMM, cp.async double-buffered ----------
// zbuf[m,o] += sum_k A[m,k]*B[o,k], 3-term bf16 split, fp32 register accum.
// grid (16 m-tiles of 128, 48 k-splits of 1536), 256 thr, 24 chunks of k=64.
#define HB_A_HI 0
#define HB_A_LO 16384
#define HB_B_HI 32768
#define HB_B_LO 40960
#define HB_STRIDE 49152
#define HB_SMEM (2 * HB_STRIDE)   // 98304
#define HB_CHUNKS 24

__device__ __forceinline__ void ldsm4(uint32_t* f, uint32_t addr) {
    asm volatile("ldmatrix.sync.aligned.m8n8.x4.shared.b16 {%0,%1,%2,%3}, [%4];"
                 : "=r"(f[0]), "=r"(f[1]), "=r"(f[2]), "=r"(f[3]) : "r"(addr));
}
__device__ __forceinline__ void mma16816(float* c, const uint32_t* a,
                                         uint32_t b0, uint32_t b1) {
    asm volatile(
        "mma.sync.aligned.m16n8k16.row.col.f32.bf16.bf16.f32 "
        "{%0,%1,%2,%3}, {%4,%5,%6,%7}, {%8,%9}, {%0,%1,%2,%3};"
        : "+f"(c[0]), "+f"(c[1]), "+f"(c[2]), "+f"(c[3])
        : "r"(a[0]), "r"(a[1]), "r"(a[2]), "r"(a[3]), "r"(b0), "r"(b1));
}

__global__ void __launch_bounds__(256) hmma_gemm_kernel() {
    extern __shared__ char smc[];
    const uint32_t sbase = smem_u32(smc);
    const int tid = threadIdx.x;
    const int wid = tid >> 5, lane = tid & 31;
    const int m0 = blockIdx.x * 128;
    const size_t k0 = (size_t)blockIdx.y * 1536;
    const int rit = lane & 7, ti = lane >> 3;

    // precomputed per-thread load indices
    const int lr = tid >> 3, lq = tid & 7;   // A: rows lr, lr+32, lr+64, lr+96
    const uint32_t lso = (uint32_t)(((lq ^ (lr & 7)) << 4));

    float acc[8][4];
#pragma unroll
    for (int i = 0; i < 8; ++i)
#pragma unroll
        for (int j = 0; j < 4; ++j) acc[i][j] = 0.f;

    // --- async chunk loader ---
    auto issue_chunk = [&](int ch, int sel) {
        const size_t kc = k0 + (size_t)ch * 64;
        const uint32_t bb = sbase + sel * HB_STRIDE;
#pragma unroll
        for (int it = 0; it < 4; ++it) {
            int r = lr + it * 32;
            size_t goff = (size_t)(m0 + r) * RELK + kc + lq * 8;
            uint32_t so = (uint32_t)(r * 128) + lso;
            cpa16(bb + HB_A_HI + so, &g_Ahi[goff]);
            cpa16(bb + HB_A_LO + so, &g_Alo[goff]);
        }
        if (tid < 128) {
            // B: 64 rows x 64k: 512 16B segs per array; 128 thr x 4 segs
#pragma unroll
            for (int it = 0; it < 2; ++it) {
                int idx = it * 128 + tid;
                int r = idx >> 3, q = idx & 7;
                size_t goff = (size_t)r * RELK + kc + q * 8;
                uint32_t so = (uint32_t)(r * 128 + ((q ^ (r & 7)) << 4));
                cpa16(bb + HB_B_HI + so, &g_Bhi[goff]);
                cpa16(bb + HB_B_LO + so, &g_Blo[goff]);
            }
        } else {
#pragma unroll
            for (int it = 0; it < 2; ++it) {
                int idx = it * 128 + (tid - 128) + 256;
                int r = idx >> 3, q = idx & 7;
                size_t goff = (size_t)r * RELK + kc + q * 8;
                uint32_t so = (uint32_t)(r * 128 + ((q ^ (r & 7)) << 4));
                cpa16(bb + HB_B_HI + so, &g_Bhi[goff]);
                cpa16(bb + HB_B_LO + so, &g_Blo[goff]);
            }
        }
        asm volatile("cp.async.commit_group;" ::: "memory");
    };

    issue_chunk(0, 0);
    for (int ch = 0; ch < HB_CHUNKS; ++ch) {
        if (ch + 1 < HB_CHUNKS) {
            issue_chunk(ch + 1, (ch + 1) & 1);
            asm volatile("cp.async.wait_group 1;" ::: "memory");
        } else {
            asm volatile("cp.async.wait_group 0;" ::: "memory");
        }
        __syncthreads();

        const uint32_t bb = sbase + (ch & 1) * HB_STRIDE;
#pragma unroll
        for (int ks = 0; ks < 4; ++ks) {
            uint32_t ahi[4], alo[4];
            {
                int r  = (wid << 4) + ((ti & 1) << 3) + rit;
                int kb = 2 * ks + (ti >> 1);
                uint32_t so = (uint32_t)(r * 128 + ((kb ^ (r & 7)) << 4));
                ldsm4(ahi, bb + HB_A_HI + so);
                ldsm4(alo, bb + HB_A_LO + so);
            }
#pragma unroll
            for (int nt2 = 0; nt2 < 4; ++nt2) {
                uint32_t bhi[4], blo[4];
                int n  = (nt2 << 4) + ((ti >> 1) << 3) + rit;
                int kb = 2 * ks + (ti & 1);
                uint32_t so = (uint32_t)(n * 128 + ((kb ^ (n & 7)) << 4));
                ldsm4(bhi, bb + HB_B_HI + so);
                ldsm4(blo, bb + HB_B_LO + so);
                mma16816(acc[2 * nt2], ahi, bhi[0], bhi[1]);
                mma16816(acc[2 * nt2], ahi, blo[0], blo[1]);
                mma16816(acc[2 * nt2], alo, bhi[0], bhi[1]);
                mma16816(acc[2 * nt2 + 1], ahi, bhi[2], bhi[3]);
                mma16816(acc[2 * nt2 + 1], ahi, blo[2], blo[3]);
                mma16816(acc[2 * nt2 + 1], alo, bhi[2], bhi[3]);
            }
        }
        __syncthreads();
    }

    // epilogue
    const int grp = lane >> 2, tig = lane & 3;
    const int m = m0 + wid * 16 + grp;
#pragma unroll
    for (int nt = 0; nt < 8; ++nt) {
        int o = nt * 8 + 2 * tig;
        atomicAdd(&g_zbuf[(size_t)m * 64 + o],           acc[nt][0]);
        atomicAdd(&g_zbuf[(size_t)m * 64 + o + 1],       acc[nt][1]);
        atomicAdd(&g_zbuf[(size_t)(m + 8) * 64 + o],     acc[nt][2]);
        atomicAdd(&g_zbuf[(size_t)(m + 8) * 64 + o + 1], acc[nt][3]);
    }
}

__global__ void scan_kernel(float* __restrict__ out, const float* __restrict__ pa1) {
    const int b = blockIdx.x;
    const int o = threadIdx.x;
    const float a1v = *pa1;
    const float z0o = g_z0[o], cc = g_cconst[o];
    float acc = 0.f, p = 1.f;
#pragma unroll
    for (int t = 0; t < 16; ++t) {
        p *= a1v;
        acc = fmaf(a1v, acc, g_zbuf[(size_t)(t * 128 + b) * 64 + o]);
        out[(size_t)(t * 128 + b) * 64 + o] = fmaf(p, z0o, acc + cc);
    }
}

extern "C" void kernel_launch(void* const* d_in, const int* in_sizes, int n_in,
                              void* d_out, int out_size) {
    const float* x         = (const float*)d_in[0];
    const float* Wqkv      = (const float*)d_in[1];
    const float* bqkv      = (const float*)d_in[2];
    const float* ln_g      = (const float*)d_in[3];
    const float* ln_b      = (const float*)d_in[4];
    const float* a1        = (const float*)d_in[5];
    const float* a2        = (const float*)d_in[6];
    const float* a3        = (const float*)d_in[7];
    const float* W2        = (const float*)d_in[8];
    const float* b2        = (const float*)d_in[9];
    const float* Wr        = (const float*)d_in[10];
    const float* br        = (const float*)d_in[11];
    const float* W3        = (const float*)d_in[12];
    const float* b3        = (const float*)d_in[13];
    const float* item_bias = (const float*)d_in[14];
    const float* rel_bias  = (const float*)d_in[15];
    float* out = (float*)d_out;

    cudaFuncSetAttribute(step_kernel, cudaFuncAttributeMaxDynamicSharedMemorySize,
                         STEP_SMEM_BYTES);
    cudaFuncSetAttribute(hmma_gemm_kernel, cudaFuncAttributeMaxDynamicSharedMemorySize,
                         HB_SMEM);

    init_kernel<<<512, 256>>>(rel_bias);                                        // 1
    step_kernel<<<128, 384, STEP_SMEM_BYTES>>>(x, Wqkv, bqkv, ln_g, ln_b,
                                               a1, a2, a3, W2, b2, item_bias);  // 2
    c2_kernel<<<dim3(288, 8), 256>>>(Wr, W3);                                   // 3
    hmma_gemm_kernel<<<dim3(16, 48), 256, HB_SMEM>>>();                         // 4 (profiled)
    z0_kernel<<<64, 256>>>(rel_bias);                                           // 5
    cconst_kernel<<<1, 64>>>(br, W3, b3);                                       // 6
    scan_kernel<<<128, 64>>>(out, a1);                                          // 7
}

// round 15
// speedup vs baseline: 2.0332x; 1.0549x over previous
#include <cuda_runtime.h>
#include <cuda_bf16.h>
#include <cstdint>

typedef unsigned long long ull;

#define RELK 73728

// ---------------- smem layout for step_kernel (float offsets), 768 threads ---
#define SM_MI     0        // 96*100
#define SM_RELSUM 9600     // 9216
#define SM_TDUP   18816    // 12288 floats = 6144 ull
#define SM_QKVT   31104    // 24*100
#define SM_WQT    33504    // 24*100
#define SM_LG     35904    // 2304
#define SM_LB     38208    // 2304
#define SM_GPART  40512    // 16*768 = 12288
#define SM_XTS    52800    // 96
#define SM_VTR8   52896    // 768
#define SM_VTRF   53664    // 96
#define SM_XW     53760    // 32
#define SM_BQ     53792    // 32
#define SM_B2S    53824    // 96
#define SM_RED    53920    // 64
#define STEP_SMEM_FLOATS 53984
#define STEP_SMEM_BYTES (STEP_SMEM_FLOATS * 4)   // 215,936 B

// ---------------- device scratch (allocation-free rule) ----------------
__device__ float g_C2[(size_t)8 * 9216 * 64];                  // 18.9MB
__device__ float g_cconst[64];
__device__ float g_relsum0[9216];
__device__ float g_z0[64];
__device__ float g_zbuf[(size_t)2048 * 64];
__device__ __nv_bfloat16 g_Ahi[(size_t)2048 * RELK];           // 302MB
__device__ __nv_bfloat16 g_Alo[(size_t)2048 * RELK];           // 302MB
__device__ __nv_bfloat16 g_Bhi[(size_t)64 * RELK];             // 9.4MB  [o][k]
__device__ __nv_bfloat16 g_Blo[(size_t)64 * RELK];             // 9.4MB

// ---------------- f32x2 packed helpers ----------------
__device__ __forceinline__ ull pk2(float x, float y) {
    ull r;
    asm("mov.b64 %0, {%1, %2};" : "=l"(r) : "f"(x), "f"(y));
    return r;
}
__device__ __forceinline__ void fma2(ull& d, ull a, ull b) {
    asm("fma.rn.f32x2 %0, %1, %2, %0;" : "+l"(d) : "l"(a), "l"(b));
}
__device__ __forceinline__ void add2(ull& d, ull a) {
    asm("add.rn.f32x2 %0, %0, %1;" : "+l"(d) : "l"(a));
}
__device__ __forceinline__ void upk2(float& lo, float& hi, ull v) {
    asm("mov.b64 {%0, %1}, %2;" : "=f"(lo), "=f"(hi) : "l"(v));
}
__device__ __forceinline__ uint32_t smem_u32(const void* p) {
    uint32_t a;
    asm("{ .reg .u64 t; cvta.to.shared.u64 t, %1; cvt.u32.u64 %0, t; }"
        : "=r"(a) : "l"(p));
    return a;
}
__device__ __forceinline__ void cpa16(uint32_t dst, const void* src) {
    asm volatile("cp.async.cg.shared.global [%0], [%1], 16;"
                 :: "r"(dst), "l"(__cvta_generic_to_global(src)) : "memory");
}

// ---- combined init (launch #1) ----
__global__ void init_kernel(const float* __restrict__ rb) {
    int idx = blockIdx.x * 256 + threadIdx.x;   // grid 512
    if (idx < 9216) {
        float s = 0.f;
#pragma unroll
        for (int n = 0; n < 8; ++n) s += rb[n * 9216 + idx];
        g_relsum0[idx] = s;
    }
    g_zbuf[idx] = 0.f;
    if (idx < 64) g_z0[idx] = 0.f;
}

// ---- C2 build + transposed bf16 hi/lo + z0 partials (launch #2) ----
__global__ void __launch_bounds__(256, 1) c2_kernel(const float* __restrict__ Wr,
                                                    const float* __restrict__ W3,
                                                    const float* __restrict__ rb) {
    __shared__ float Wrs[32 * 96];
    __shared__ float W3s[96 * 64];
    __shared__ float smt[32][65];
    __shared__ float zz[256];
    const int tid = threadIdx.x;
    const int de0 = blockIdx.x * 32;   // 288 de-tiles
    const int n = blockIdx.y;          // 8
    for (int p = tid; p < 3072; p += 256) Wrs[p] = Wr[de0 * 96 + p];
    for (int p = tid; p < 6144; p += 256) W3s[p] = W3[n * 6144 + p];
    __syncthreads();
    const int o = tid & 63, de_b = tid >> 6;
    float acc[8];
#pragma unroll
    for (int i = 0; i < 8; ++i) acc[i] = 0.f;
    for (int r = 0; r < 96; ++r) {
        float bv = W3s[r * 64 + o];
#pragma unroll
        for (int i = 0; i < 8; ++i)
            acc[i] = fmaf(Wrs[(de_b + 4 * i) * 96 + r], bv, acc[i]);
    }
    float zp = 0.f;
#pragma unroll
    for (int i = 0; i < 8; ++i) {
        int de = de0 + de_b + 4 * i;
        g_C2[((size_t)n * 9216 + de) * 64 + o] = acc[i];
        smt[de_b + 4 * i][o] = acc[i];
        zp = fmaf(rb[n * 9216 + de], acc[i], zp);
    }
    zz[tid] = zp;
    __syncthreads();
    if (tid < 64) {
        float s = zz[o] + zz[64 + o] + zz[128 + o] + zz[192 + o];
        atomicAdd(&g_z0[o], s);
    }
    // transposed bf16 hi/lo: row o, k = n*9216 + de
    {
        const int o2 = tid >> 2, seg = tid & 3;
        float v[8];
#pragma unroll
        for (int r = 0; r < 8; ++r) v[r] = smt[seg * 8 + r][o2];
        uint32_t hw[4], lw[4];
#pragma unroll
        for (int p = 0; p < 4; ++p) {
            __nv_bfloat162 h = __floats2bfloat162_rn(v[2 * p], v[2 * p + 1]);
            float2 hf = __bfloat1622float2(h);
            __nv_bfloat162 l = __floats2bfloat162_rn(v[2 * p] - hf.x,
                                                     v[2 * p + 1] - hf.y);
            hw[p] = *(uint32_t*)&h;
            lw[p] = *(uint32_t*)&l;
        }
        size_t base = (size_t)o2 * RELK + (size_t)n * 9216 + de0 + seg * 8;
        *(uint4*)&g_Bhi[base] = make_uint4(hw[0], hw[1], hw[2], hw[3]);
        *(uint4*)&g_Blo[base] = make_uint4(lw[0], lw[1], lw[2], lw[3]);
    }
}

__global__ void cconst_kernel(const float* __restrict__ br,
                              const float* __restrict__ W3,
                              const float* __restrict__ b3) {
    int o = threadIdx.x;
    float acc = b3[o];
    for (int nr = 0; nr < 768; ++nr)
        acc = fmaf(br[nr % 96], W3[nr * 64 + o], acc);
    g_cconst[o] = acc;
}

// ---------------- phase 1: recurrent kernel, 768 threads (launch #4) ---------
__global__ void __launch_bounds__(768, 1) step_kernel(
    const float* __restrict__ x, const float* __restrict__ Wqkv,
    const float* __restrict__ bqkv, const float* __restrict__ ln_g,
    const float* __restrict__ ln_b, const float* __restrict__ pa1,
    const float* __restrict__ pa2, const float* __restrict__ pa3,
    const float* __restrict__ W2, const float* __restrict__ b2,
    const float* __restrict__ item_bias)
{
    extern __shared__ float sm[];
    float* Mi     = sm + SM_MI;
    float* relsum = sm + SM_RELSUM;
    ull*   tdup   = (ull*)(sm + SM_TDUP);
    float* qkvT   = sm + SM_QKVT;
    float* WqT    = sm + SM_WQT;
    float* lg     = sm + SM_LG;
    float* lb     = sm + SM_LB;
    float* Gpart  = sm + SM_GPART;
    float* xts    = sm + SM_XTS;
    float* vtr8   = sm + SM_VTR8;
    float* vtrF   = sm + SM_VTRF;
    float* xw     = sm + SM_XW;
    float* bq     = sm + SM_BQ;
    float* b2s    = sm + SM_B2S;
    float* red    = sm + SM_RED;

    const int tid = threadIdx.x;
    const int b = blockIdx.x;
    const float a1v = *pa1, a2v = *pa2, a3v = *pa3;

    for (int idx = tid; idx < 2304; idx += 768) {
        int f = idx / 24, h = idx % 24;
        WqT[h * 100 + f] = Wqkv[idx];
        lg[idx] = ln_g[idx];
        lb[idx] = ln_b[idx];
    }
    if (tid < 24) bq[tid] = bqkv[tid];
    if (tid < 96) b2s[tid] = b2[tid];
    for (int idx = tid; idx < 9216; idx += 768) {
        Mi[(idx / 96) * 100 + (idx % 96)] = item_bias[idx];
        relsum[idx] = g_relsum0[idx];
    }
    __syncthreads();

    for (int t = 0; t < 16; ++t) {
        if (tid < 96) xts[tid] = x[(t * 128 + b) * 96 + tid];
        __syncthreads();

        // op1: Mi += x x^T
        for (int idx = tid; idx < 9216; idx += 768) {
            int d = idx / 96, f = idx % 96;
            Mi[d * 100 + f] = fmaf(xts[d], xts[f], Mi[d * 100 + f]);
        }
        __syncthreads();

        // Vtr partials (8 d-groups of 12) and xw
        {
            int f = tid % 96, q = tid / 96;
            int d0 = q * 12;
            float acc = 0.f;
#pragma unroll 4
            for (int d = d0; d < d0 + 12; ++d)
                acc = fmaf(Mi[d * 100 + f], relsum[d * 96 + f], acc);
            vtr8[q * 96 + f] = acc;
        }
        if (tid < 24) {
            float acc = 0.f;
            for (int f = 0; f < 96; ++f)
                acc = fmaf(xts[f], WqT[tid * 100 + f], acc);
            xw[tid] = acc;
        }
        __syncthreads();
        if (tid < 96) {
            float s = vtr8[tid];
#pragma unroll
            for (int q = 1; q < 8; ++q) s += vtr8[q * 96 + tid];
            vtrF[tid] = s;
        }
        __syncthreads();

        // op3: 8 h-groups of 3; thread = (hg, d)
        float s1 = 0.f, s2 = 0.f;
        {
            const int hg = tid / 96;       // 0..7
            const int d  = tid % 96;
            const int h0 = hg * 3;
            ull acc[3][2];
#pragma unroll
            for (int i = 0; i < 3; ++i) { acc[i][0] = 0ull; acc[i][1] = 0ull; }
#pragma unroll 6
            for (int fq = 0; fq < 24; ++fq) {
                ulonglong2 m2 = *(const ulonglong2*)&Mi[d * 100 + 4 * fq];
#pragma unroll
                for (int hh = 0; hh < 3; ++hh) {
                    ulonglong2 w2v = *(const ulonglong2*)&WqT[(h0 + hh) * 100 + 4 * fq];
                    fma2(acc[hh][0], m2.x, w2v.x);
                    fma2(acc[hh][1], m2.y, w2v.y);
                }
            }
            const float vtrd = vtrF[d];
#pragma unroll
            for (int hh = 0; hh < 3; ++hh) {
                float l0, h0f, l1, h1f;
                upk2(l0, h0f, acc[hh][0]);
                upk2(l1, h1f, acc[hh][1]);
                int h = h0 + hh;
                float v = (l0 + h0f) + (l1 + h1f) + bq[h] + a2v * vtrd * xw[h];
                qkvT[h * 100 + d] = v;
                s1 += v;
                s2 = fmaf(v, v, s2);
            }
        }
        // LN reduction (24 warps)
#pragma unroll
        for (int o = 16; o > 0; o >>= 1) {
            s1 += __shfl_down_sync(0xffffffffu, s1, o);
            s2 += __shfl_down_sync(0xffffffffu, s2, o);
        }
        if ((tid & 31) == 0) { red[(tid >> 5) * 2] = s1; red[(tid >> 5) * 2 + 1] = s2; }
        __syncthreads();
        if (tid == 0) {
            float S = 0.f, SS = 0.f;
            for (int w = 0; w < 24; ++w) { S += red[w * 2]; SS += red[w * 2 + 1]; }
            float mu = S * (1.f / 2304.f);
            float var = SS * (1.f / 2304.f) - mu * mu;
            red[62] = mu;
            red[63] = rsqrtf(var + 1e-5f);
        }
        __syncthreads();
        const float mu = red[62], rstd = red[63];

        // op4: LN apply
        for (int idx = tid; idx < 2304; idx += 768) {
            int h = idx / 96, d = idx % 96;
            float v = qkvT[h * 100 + d];
            qkvT[h * 100 + d] = (v - mu) * rstd * lg[d * 24 + h] + lb[d * 24 + h];
        }
        __syncthreads();

        // op5: tdup
        for (int idx = tid; idx < 6144; idx += 768) {
            int j = idx & 7, d = (idx >> 3) % 96, n = idx / 768;
            float p = qkvT[n * 100 + d] * qkvT[(8 + j) * 100 + d];
            float e = __expf(2.f * p);
            float tv = 1.f - 2.f / (e + 1.f);
            tdup[idx] = pk2(tv, tv);
        }
        __syncthreads();

        // op6: 16 groups x 48 nd; 2 f per thread (f-pair fp = tid%48)
        {
            const int fp = tid % 48;
            const int g  = tid / 48;      // 0..15
            const int f0 = 2 * fp;
            ull acc[8];
#pragma unroll
            for (int j = 0; j < 8; ++j) acc[j] = 0ull;
            const float* w2p = W2 + (size_t)(g * 48) * 96 + f0;
            const ulonglong2* tp = (const ulonglong2*)&tdup[(g * 48) * 8];
#pragma unroll 4
            for (int m = 0; m < 48; ++m) {
                float2 wv = *(const float2*)&w2p[(size_t)m * 96];
                ull w01 = pk2(wv.x, wv.y);
                ulonglong2 t01 = tp[m * 4 + 0];
                ulonglong2 t23 = tp[m * 4 + 1];
                ulonglong2 t45 = tp[m * 4 + 2];
                ulonglong2 t67 = tp[m * 4 + 3];
                fma2(acc[0], t01.x, w01); fma2(acc[1], t01.y, w01);
                fma2(acc[2], t23.x, w01); fma2(acc[3], t23.y, w01);
                fma2(acc[4], t45.x, w01); fma2(acc[5], t45.y, w01);
                fma2(acc[6], t67.x, w01); fma2(acc[7], t67.y, w01);
            }
#pragma unroll
            for (int j = 0; j < 8; ++j)
                *(ull*)&Gpart[g * 768 + j * 96 + f0] = acc[j];
        }
        __syncthreads();
        // reduce 16 partials -> G
        {
            float s = Gpart[tid];
#pragma unroll
            for (int g2 = 1; g2 < 16; ++g2) s += Gpart[g2 * 768 + tid];
            __syncthreads();
            Gpart[tid] = s;
        }
        __syncthreads();

        // op7: Mi[e][f] += a3*( sum_j v[j][e]*G[j][f] + b2[f] ); 8 f-parts of 12
        {
            const int e = tid >> 3, part = tid & 7;
            const int f0b = part * 12;
            ull vp[8];
#pragma unroll
            for (int j = 0; j < 8; ++j) {
                float ve = qkvT[(16 + j) * 100 + e];
                vp[j] = pk2(ve, ve);
            }
#pragma unroll 3
            for (int q = 0; q < 6; ++q) {
                int f0 = f0b + q * 2;
                ull acc = 0ull;
#pragma unroll
                for (int j = 0; j < 8; ++j)
                    fma2(acc, vp[j], *(const ull*)&Gpart[j * 96 + f0]);
                float lo, hi;
                upk2(lo, hi, acc);
                Mi[e * 100 + f0]     = fmaf(a3v, lo + b2s[f0],     Mi[e * 100 + f0]);
                Mi[e * 100 + f0 + 1] = fmaf(a3v, hi + b2s[f0 + 1], Mi[e * 100 + f0 + 1]);
            }
        }

        // op8: R0 -> bf16 hi/lo (48 e-pairs x 16 nd-groups); relsum update
        {
            const int ep = tid % 48;
            const int g  = tid / 48;      // 0..15
            const int e0 = 2 * ep;
            ull vP[8];
#pragma unroll
            for (int j = 0; j < 8; ++j)
                vP[j] = *(const ull*)&qkvT[(16 + j) * 100 + e0];
            const size_t mrow = (size_t)(t * 128 + b) * RELK;
            ull racc[6];
#pragma unroll
            for (int mm = 0; mm < 6; ++mm) racc[mm] = 0ull;
#pragma unroll 4
            for (int it = g; it < 768; it += 16) {
                const ulonglong2* tp = (const ulonglong2*)&tdup[it * 8];
                ulonglong2 t01 = tp[0], t23 = tp[1], t45 = tp[2], t67 = tp[3];
                ull a0 = 0ull;
                fma2(a0, t01.x, vP[0]); fma2(a0, t01.y, vP[1]);
                fma2(a0, t23.x, vP[2]); fma2(a0, t23.y, vP[3]);
                fma2(a0, t45.x, vP[4]); fma2(a0, t45.y, vP[5]);
                fma2(a0, t67.x, vP[6]); fma2(a0, t67.y, vP[7]);
                float f0, f1;
                upk2(f0, f1, a0);
                __nv_bfloat162 h01 = __floats2bfloat162_rn(f0, f1);
                float2 hf01 = __bfloat1622float2(h01);
                __nv_bfloat162 l01 = __floats2bfloat162_rn(f0 - hf01.x, f1 - hf01.y);
                *(uint32_t*)&g_Ahi[mrow + (size_t)it * 96 + e0] = *(uint32_t*)&h01;
                *(uint32_t*)&g_Alo[mrow + (size_t)it * 96 + e0] = *(uint32_t*)&l01;
                int mm = (it >> 4) % 6;
                add2(racc[mm], a0);
            }
            const ull a1P = pk2(a1v, a1v);
#pragma unroll
            for (int mm = 0; mm < 6; ++mm) {
                int d = g + 16 * mm;
                ull old = *(const ull*)&relsum[d * 96 + e0];
                fma2(racc[mm], a1P, old);
                *(ull*)&relsum[d * 96 + e0] = racc[mm];
            }
        }
        __syncthreads();
    }
}

// ---------------- phase 2: HMMA bf16 GEMM, cp.async double-buffered ----------
#define HB_A_HI 0
#define HB_A_LO 16384
#define HB_B_HI 32768
#define HB_B_LO 40960
#define HB_STRIDE 49152
#define HB_SMEM (2 * HB_STRIDE)   // 98304
#define HB_CHUNKS 24

__device__ __forceinline__ void ldsm4(uint32_t* f, uint32_t addr) {
    asm volatile("ldmatrix.sync.aligned.m8n8.x4.shared.b16 {%0,%1,%2,%3}, [%4];"
                 : "=r"(f[0]), "=r"(f[1]), "=r"(f[2]), "=r"(f[3]) : "r"(addr));
}
__device__ __forceinline__ void mma16816(float* c, const uint32_t* a,
                                         uint32_t b0, uint32_t b1) {
    asm volatile(
        "mma.sync.aligned.m16n8k16.row.col.f32.bf16.bf16.f32 "
        "{%0,%1,%2,%3}, {%4,%5,%6,%7}, {%8,%9}, {%0,%1,%2,%3};"
        : "+f"(c[0]), "+f"(c[1]), "+f"(c[2]), "+f"(c[3])
        : "r"(a[0]), "r"(a[1]), "r"(a[2]), "r"(a[3]), "r"(b0), "r"(b1));
}

__global__ void __launch_bounds__(256) hmma_gemm_kernel() {
    extern __shared__ char smc[];
    const uint32_t sbase = smem_u32(smc);
    const int tid = threadIdx.x;
    const int wid = tid >> 5, lane = tid & 31;
    const int m0 = blockIdx.x * 128;
    const size_t k0 = (size_t)blockIdx.y * 1536;
    const int rit = lane & 7, ti = lane >> 3;

    const int lr = tid >> 3, lq = tid & 7;
    const uint32_t lso = (uint32_t)(((lq ^ (lr & 7)) << 4));

    float acc[8][4];
#pragma unroll
    for (int i = 0; i < 8; ++i)
#pragma unroll
        for (int j = 0; j < 4; ++j) acc[i][j] = 0.f;

    auto issue_chunk = [&](int ch, int sel) {
        const size_t kc = k0 + (size_t)ch * 64;
        const uint32_t bb = sbase + sel * HB_STRIDE;
#pragma unroll
        for (int it = 0; it < 4; ++it) {
            int r = lr + it * 32;
            size_t goff = (size_t)(m0 + r) * RELK + kc + lq * 8;
            uint32_t so = (uint32_t)(r * 128) + lso;
            cpa16(bb + HB_A_HI + so, &g_Ahi[goff]);
            cpa16(bb + HB_A_LO + so, &g_Alo[goff]);
        }
        if (tid < 128) {
#pragma unroll
            for (int it = 0; it < 2; ++it) {
                int idx = it * 128 + tid;
                int r = idx >> 3, q = idx & 7;
                size_t goff = (size_t)r * RELK + kc + q * 8;
                uint32_t so = (uint32_t)(r * 128 + ((q ^ (r & 7)) << 4));
                cpa16(bb + HB_B_HI + so, &g_Bhi[goff]);
                cpa16(bb + HB_B_LO + so, &g_Blo[goff]);
            }
        } else {
#pragma unroll
            for (int it = 0; it < 2; ++it) {
                int idx = it * 128 + (tid - 128) + 256;
                int r = idx >> 3, q = idx & 7;
                size_t goff = (size_t)r * RELK + kc + q * 8;
                uint32_t so = (uint32_t)(r * 128 + ((q ^ (r & 7)) << 4));
                cpa16(bb + HB_B_HI + so, &g_Bhi[goff]);
                cpa16(bb + HB_B_LO + so, &g_Blo[goff]);
            }
        }
        asm volatile("cp.async.commit_group;" ::: "memory");
    };

    issue_chunk(0, 0);
    for (int ch = 0; ch < HB_CHUNKS; ++ch) {
        if (ch + 1 < HB_CHUNKS) {
            issue_chunk(ch + 1, (ch + 1) & 1);
            asm volatile("cp.async.wait_group 1;" ::: "memory");
        } else {
            asm volatile("cp.async.wait_group 0;" ::: "memory");
        }
        __syncthreads();

        const uint32_t bb = sbase + (ch & 1) * HB_STRIDE;
#pragma unroll
        for (int ks = 0; ks < 4; ++ks) {
            uint32_t ahi[4], alo[4];
            {
                int r  = (wid << 4) + ((ti & 1) << 3) + rit;
                int kb = 2 * ks + (ti >> 1);
                uint32_t so = (uint32_t)(r * 128 + ((kb ^ (r & 7)) << 4));
                ldsm4(ahi, bb + HB_A_HI + so);
                ldsm4(alo, bb + HB_A_LO + so);
            }
#pragma unroll
            for (int nt2 = 0; nt2 < 4; ++nt2) {
                uint32_t bhi[4], blo[4];
                int n  = (nt2 << 4) + ((ti >> 1) << 3) + rit;
                int kb = 2 * ks + (ti & 1);
                uint32_t so = (uint32_t)(n * 128 + ((kb ^ (n & 7)) << 4));
                ldsm4(bhi, bb + HB_B_HI + so);
                ldsm4(blo, bb + HB_B_LO + so);
                mma16816(acc[2 * nt2], ahi, bhi[0], bhi[1]);
                mma16816(acc[2 * nt2], ahi, blo[0], blo[1]);
                mma16816(acc[2 * nt2], alo, bhi[0], bhi[1]);
                mma16816(acc[2 * nt2 + 1], ahi, bhi[2], bhi[3]);
                mma16816(acc[2 * nt2 + 1], ahi, blo[2], blo[3]);
                mma16816(acc[2 * nt2 + 1], alo, bhi[2], bhi[3]);
            }
        }
        __syncthreads();
    }

    const int grp = lane >> 2, tig = lane & 3;
    const int m = m0 + wid * 16 + grp;
#pragma unroll
    for (int nt = 0; nt < 8; ++nt) {
        int o = nt * 8 + 2 * tig;
        atomicAdd(&g_zbuf[(size_t)m * 64 + o],           acc[nt][0]);
        atomicAdd(&g_zbuf[(size_t)m * 64 + o + 1],       acc[nt][1]);
        atomicAdd(&g_zbuf[(size_t)(m + 8) * 64 + o],     acc[nt][2]);
        atomicAdd(&g_zbuf[(size_t)(m + 8) * 64 + o + 1], acc[nt][3]);
    }
}

__global__ void scan_kernel(float* __restrict__ out, const float* __restrict__ pa1) {
    const int b = blockIdx.x;
    const int o = threadIdx.x;
    const float a1v = *pa1;
    const float z0o = g_z0[o], cc = g_cconst[o];
    float acc = 0.f, p = 1.f;
#pragma unroll
    for (int t = 0; t < 16; ++t) {
        p *= a1v;
        acc = fmaf(a1v, acc, g_zbuf[(size_t)(t * 128 + b) * 64 + o]);
        out[(size_t)(t * 128 + b) * 64 + o] = fmaf(p, z0o, acc + cc);
    }
}

extern "C" void kernel_launch(void* const* d_in, const int* in_sizes, int n_in,
                              void* d_out, int out_size) {
    const float* x         = (const float*)d_in[0];
    const float* Wqkv      = (const float*)d_in[1];
    const float* bqkv      = (const float*)d_in[2];
    const float* ln_g      = (const float*)d_in[3];
    const float* ln_b      = (const float*)d_in[4];
    const float* a1        = (const float*)d_in[5];
    const float* a2        = (const float*)d_in[6];
    const float* a3        = (const float*)d_in[7];
    const float* W2        = (const float*)d_in[8];
    const float* b2        = (const float*)d_in[9];
    const float* Wr        = (const float*)d_in[10];
    const float* br        = (const float*)d_in[11];
    const float* W3        = (const float*)d_in[12];
    const float* b3        = (const float*)d_in[13];
    const float* item_bias = (const float*)d_in[14];
    const float* rel_bias  = (const float*)d_in[15];
    float* out = (float*)d_out;

    cudaFuncSetAttribute(step_kernel, cudaFuncAttributeMaxDynamicSharedMemorySize,
                         STEP_SMEM_BYTES);
    cudaFuncSetAttribute(hmma_gemm_kernel, cudaFuncAttributeMaxDynamicSharedMemorySize,
                         HB_SMEM);

    init_kernel<<<512, 256>>>(rel_bias);                                        // 1
    c2_kernel<<<dim3(288, 8), 256>>>(Wr, W3, rel_bias);                         // 2
    cconst_kernel<<<1, 64>>>(br, W3, b3);                                       // 3
    step_kernel<<<128, 768, STEP_SMEM_BYTES>>>(x, Wqkv, bqkv, ln_g, ln_b,
                                               a1, a2, a3, W2, b2, item_bias);  // 4 (profiled)
    hmma_gemm_kernel<<<dim3(16, 48), 256, HB_SMEM>>>();                         // 5
    scan_kernel<<<128, 64>>>(out, a1);                                          // 6
}

// round 16
// speedup vs baseline: 2.1007x; 1.0332x over previous
#include <cuda_runtime.h>
#include <cuda_bf16.h>
#include <cstdint>

typedef unsigned long long ull;

#define RELK 73728

// ---------------- smem layout for step_kernel (float offsets), 768 threads ---
#define SM_MI     0        // 9600 (96x100)
#define SM_RELSUM 9600     // 9216
#define SM_TDUP   18816    // 12288 (6144 ull)
#define SM_QKVT   31104    // 2400 (24x100)
#define SM_WQT    33504    // 2400
#define SM_LG     35904    // 2304
#define SM_LB     38208    // 2304
#define SM_GPART  40512    // 12288 (16x768)
#define SM_P      52800    // 2400 (24x100)  qkv-pre = Mi@Wqkv
#define SM_GWP    55200    // 768 (4x192)
#define SM_GW     55968    // 192
#define SM_XTS    56160    // 96
#define SM_VTR8   56256    // 768
#define SM_VTRF   57024    // 96
#define SM_XW     57120    // 32
#define SM_BQ     57152    // 32
#define SM_B2S    57184    // 96
#define SM_B2W    57280    // 32
#define SM_RED    57312    // 64
#define STEP_SMEM_FLOATS 57376
#define STEP_SMEM_BYTES (STEP_SMEM_FLOATS * 4)   // 229,504 B

// ---------------- device scratch (allocation-free rule) ----------------
__device__ float g_C2[(size_t)8 * 9216 * 64];                  // 18.9MB
__device__ float g_cconst[64];
__device__ float g_relsum0[9216];
__device__ float g_z0[64];
__device__ float g_zbuf[(size_t)2048 * 64];
__device__ ull   g_W2p[(size_t)768 * 48];                      // (w,w) pairs, 294KB
__device__ __nv_bfloat16 g_Ahi[(size_t)2048 * RELK];           // 302MB
__device__ __nv_bfloat16 g_Alo[(size_t)2048 * RELK];           // 302MB
__device__ __nv_bfloat16 g_Bhi[(size_t)64 * RELK];             // 9.4MB  [o][k]
__device__ __nv_bfloat16 g_Blo[(size_t)64 * RELK];             // 9.4MB

// ---------------- f32x2 packed helpers ----------------
__device__ __forceinline__ ull pk2(float x, float y) {
    ull r;
    asm("mov.b64 %0, {%1, %2};" : "=l"(r) : "f"(x), "f"(y));
    return r;
}
__device__ __forceinline__ void fma2(ull& d, ull a, ull b) {
    asm("fma.rn.f32x2 %0, %1, %2, %0;" : "+l"(d) : "l"(a), "l"(b));
}
__device__ __forceinline__ void add2(ull& d, ull a) {
    asm("add.rn.f32x2 %0, %0, %1;" : "+l"(d) : "l"(a));
}
__device__ __forceinline__ void upk2(float& lo, float& hi, ull v) {
    asm("mov.b64 {%0, %1}, %2;" : "=f"(lo), "=f"(hi) : "l"(v));
}
__device__ __forceinline__ uint32_t smem_u32(const void* p) {
    uint32_t a;
    asm("{ .reg .u64 t; cvta.to.shared.u64 t, %1; cvt.u32.u64 %0, t; }"
        : "=r"(a) : "l"(p));
    return a;
}
__device__ __forceinline__ void cpa16(uint32_t dst, const void* src) {
    asm volatile("cp.async.cg.shared.global [%0], [%1], 16;"
                 :: "r"(dst), "l"(__cvta_generic_to_global(src)) : "memory");
}

// ---- combined init: relsum0, zbuf, z0, W2 pack (launch #1) ----
__global__ void init_kernel(const float* __restrict__ rb,
                            const float* __restrict__ W2) {
    int idx = blockIdx.x * 256 + threadIdx.x;   // grid 512 -> 131072
    if (idx < 9216) {
        float s = 0.f;
#pragma unroll
        for (int n = 0; n < 8; ++n) s += rb[n * 9216 + idx];
        g_relsum0[idx] = s;
    }
    g_zbuf[idx] = 0.f;
    if (idx < 64) g_z0[idx] = 0.f;
    if (idx < 36864) {
        int row = idx / 48, fp = idx % 48;
        float2 w = *(const float2*)&W2[row * 96 + 2 * fp];
        g_W2p[idx] = pk2(w.x, w.y);
    }
}

// ---- C2 build + transposed bf16 hi/lo + z0 partials (launch #2) ----
__global__ void __launch_bounds__(256, 1) c2_kernel(const float* __restrict__ Wr,
                                                    const float* __restrict__ W3,
                                                    const float* __restrict__ rb) {
    __shared__ float Wrs[32 * 96];
    __shared__ float W3s[96 * 64];
    __shared__ float smt[32][65];
    __shared__ float zz[256];
    const int tid = threadIdx.x;
    const int de0 = blockIdx.x * 32;   // 288 de-tiles
    const int n = blockIdx.y;          // 8
    for (int p = tid; p < 3072; p += 256) Wrs[p] = Wr[de0 * 96 + p];
    for (int p = tid; p < 6144; p += 256) W3s[p] = W3[n * 6144 + p];
    __syncthreads();
    const int o = tid & 63, de_b = tid >> 6;
    float acc[8];
#pragma unroll
    for (int i = 0; i < 8; ++i) acc[i] = 0.f;
    for (int r = 0; r < 96; ++r) {
        float bv = W3s[r * 64 + o];
#pragma unroll
        for (int i = 0; i < 8; ++i)
            acc[i] = fmaf(Wrs[(de_b + 4 * i) * 96 + r], bv, acc[i]);
    }
    float zp = 0.f;
#pragma unroll
    for (int i = 0; i < 8; ++i) {
        int de = de0 + de_b + 4 * i;
        g_C2[((size_t)n * 9216 + de) * 64 + o] = acc[i];
        smt[de_b + 4 * i][o] = acc[i];
        zp = fmaf(rb[n * 9216 + de], acc[i], zp);
    }
    zz[tid] = zp;
    __syncthreads();
    if (tid < 64) {
        float s = zz[o] + zz[64 + o] + zz[128 + o] + zz[192 + o];
        atomicAdd(&g_z0[o], s);
    }
    {
        const int o2 = tid >> 2, seg = tid & 3;
        float v[8];
#pragma unroll
        for (int r = 0; r < 8; ++r) v[r] = smt[seg * 8 + r][o2];
        uint32_t hw[4], lw[4];
#pragma unroll
        for (int p = 0; p < 4; ++p) {
            __nv_bfloat162 h = __floats2bfloat162_rn(v[2 * p], v[2 * p + 1]);
            float2 hf = __bfloat1622float2(h);
            __nv_bfloat162 l = __floats2bfloat162_rn(v[2 * p] - hf.x,
                                                     v[2 * p + 1] - hf.y);
            hw[p] = *(uint32_t*)&h;
            lw[p] = *(uint32_t*)&l;
        }
        size_t base = (size_t)o2 * RELK + (size_t)n * 9216 + de0 + seg * 8;
        *(uint4*)&g_Bhi[base] = make_uint4(hw[0], hw[1], hw[2], hw[3]);
        *(uint4*)&g_Blo[base] = make_uint4(lw[0], lw[1], lw[2], lw[3]);
    }
}

__global__ void cconst_kernel(const float* __restrict__ br,
                              const float* __restrict__ W3,
                              const float* __restrict__ b3) {
    int o = threadIdx.x;
    float acc = b3[o];
    for (int nr = 0; nr < 768; ++nr)
        acc = fmaf(br[nr % 96], W3[nr * 64 + o], acc);
    g_cconst[o] = acc;
}

// ---------------- phase 1: recurrent kernel, 768 threads (launch #4) ---------
__global__ void __launch_bounds__(768, 1) step_kernel(
    const float* __restrict__ x, const float* __restrict__ Wqkv,
    const float* __restrict__ bqkv, const float* __restrict__ ln_g,
    const float* __restrict__ ln_b, const float* __restrict__ pa1,
    const float* __restrict__ pa2, const float* __restrict__ pa3,
    const float* __restrict__ b2, const float* __restrict__ item_bias)
{
    extern __shared__ float sm[];
    float* Mi     = sm + SM_MI;
    float* relsum = sm + SM_RELSUM;
    ull*   tdup   = (ull*)(sm + SM_TDUP);
    float* qkvT   = sm + SM_QKVT;
    float* WqT    = sm + SM_WQT;
    float* lg     = sm + SM_LG;
    float* lb     = sm + SM_LB;
    float* Gpart  = sm + SM_GPART;
    float* P      = sm + SM_P;
    float* GWP    = sm + SM_GWP;
    float* GW     = sm + SM_GW;
    float* xts    = sm + SM_XTS;
    float* vtr8   = sm + SM_VTR8;
    float* vtrF   = sm + SM_VTRF;
    float* xw     = sm + SM_XW;
    float* bq     = sm + SM_BQ;
    float* b2s    = sm + SM_B2S;
    float* b2w    = sm + SM_B2W;
    float* red    = sm + SM_RED;

    const int tid = threadIdx.x;
    const int b = blockIdx.x;
    const float a1v = *pa1, a2v = *pa2, a3v = *pa3;

    // hoisted per-thread indices
    const int f96 = tid % 96, q8 = tid / 96;     // (f,d-group)/(e,h-group) maps
    const int h0  = q8 * 3;
    const int d0v = q8 * 12;
    const int fp48 = tid % 48, g16 = tid / 48;   // op6/op8
    const int e0p = 2 * fp48;
    const int jh = tid % 192, qq = tid / 192;    // GW partials
    const int jj = jh / 24, hh24 = jh % 24;
    const int e7 = tid >> 3, part7 = tid & 7;    // op7
    const int f0b7 = part7 * 12;

    // one-time loads
    for (int idx = tid; idx < 2304; idx += 768) {
        int f = idx / 24, h = idx % 24;
        WqT[h * 100 + f] = Wqkv[idx];
        lg[idx] = ln_g[idx];
        lb[idx] = ln_b[idx];
    }
    if (tid < 24) bq[tid] = bqkv[tid];
    if (tid < 96) b2s[tid] = b2[tid];
    for (int idx = tid; idx < 9216; idx += 768) {
        Mi[(idx / 96) * 100 + (idx % 96)] = item_bias[idx];
        relsum[idx] = g_relsum0[idx];
    }
    __syncthreads();

    // one-time: P = Mi@Wqkv (Mi == item_bias here), b2W
    {
        ull acc2[3][2];
#pragma unroll
        for (int i = 0; i < 3; ++i) { acc2[i][0] = 0ull; acc2[i][1] = 0ull; }
#pragma unroll 6
        for (int fq = 0; fq < 24; ++fq) {
            ulonglong2 m2 = *(const ulonglong2*)&Mi[f96 * 100 + 4 * fq];
#pragma unroll
            for (int hh = 0; hh < 3; ++hh) {
                ulonglong2 w2v = *(const ulonglong2*)&WqT[(h0 + hh) * 100 + 4 * fq];
                fma2(acc2[hh][0], m2.x, w2v.x);
                fma2(acc2[hh][1], m2.y, w2v.y);
            }
        }
#pragma unroll
        for (int hh = 0; hh < 3; ++hh) {
            float l0, h0f, l1, h1f;
            upk2(l0, h0f, acc2[hh][0]);
            upk2(l1, h1f, acc2[hh][1]);
            P[(h0 + hh) * 100 + f96] = (l0 + h0f) + (l1 + h1f);
        }
    }
    if (tid < 24) {
        float acc = 0.f;
        for (int f = 0; f < 96; ++f)
            acc = fmaf(b2s[f], WqT[tid * 100 + f], acc);
        b2w[tid] = acc;
    }
    __syncthreads();

    for (int t = 0; t < 16; ++t) {
        if (tid < 96) xts[tid] = x[(t * 128 + b) * 96 + tid];
        __syncthreads();

        // fused op1 + Vtr partials: Mi += x x^T; accv over own (d,f) cells
        {
            float accv = 0.f;
            const float xf = xts[f96];
#pragma unroll 4
            for (int d = d0v; d < d0v + 12; ++d) {
                float m = fmaf(xts[d], xf, Mi[d * 100 + f96]);
                Mi[d * 100 + f96] = m;
                accv = fmaf(m, relsum[d * 96 + f96], accv);
            }
            vtr8[q8 * 96 + f96] = accv;
        }
        if (tid < 24) {
            float acc = 0.f;
            for (int f = 0; f < 96; ++f)
                acc = fmaf(xts[f], WqT[tid * 100 + f], acc);
            xw[tid] = acc;
        }
        __syncthreads();
        if (tid < 96) {
            float s = vtr8[tid];
#pragma unroll
            for (int q = 1; q < 8; ++q) s += vtr8[q * 96 + tid];
            vtrF[tid] = s;
        }
        __syncthreads();

        // qkv from incremental P: P += x⊗xw; v = P + bq + a2*vtr*xw
        float s1 = 0.f, s2 = 0.f;
        {
            const float xd = xts[f96];
            const float vtrd = vtrF[f96];
#pragma unroll
            for (int hh = 0; hh < 3; ++hh) {
                int h = h0 + hh;
                float xwh = xw[h];
                float Pv = fmaf(xd, xwh, P[h * 100 + f96]);
                P[h * 100 + f96] = Pv;
                float v = Pv + bq[h] + a2v * vtrd * xwh;
                qkvT[h * 100 + f96] = v;
                s1 += v;
                s2 = fmaf(v, v, s2);
            }
        }
#pragma unroll
        for (int o = 16; o > 0; o >>= 1) {
            s1 += __shfl_down_sync(0xffffffffu, s1, o);
            s2 += __shfl_down_sync(0xffffffffu, s2, o);
        }
        if ((tid & 31) == 0) { red[(tid >> 5) * 2] = s1; red[(tid >> 5) * 2 + 1] = s2; }
        __syncthreads();
        if (tid == 0) {
            float S = 0.f, SS = 0.f;
            for (int w = 0; w < 24; ++w) { S += red[w * 2]; SS += red[w * 2 + 1]; }
            float mu = S * (1.f / 2304.f);
            float var = SS * (1.f / 2304.f) - mu * mu;
            red[62] = mu;
            red[63] = rsqrtf(var + 1e-5f);
        }
        __syncthreads();
        const float mu = red[62], rstd = red[63];

        // LN apply
        for (int idx = tid; idx < 2304; idx += 768) {
            int h = idx / 96, d = idx % 96;
            float v = qkvT[h * 100 + d];
            qkvT[h * 100 + d] = (v - mu) * rstd * lg[d * 24 + h] + lb[d * 24 + h];
        }
        __syncthreads();

        // op5: tdup
        for (int idx = tid; idx < 6144; idx += 768) {
            int j = idx & 7, d = (idx >> 3) % 96, n = idx / 768;
            float p = qkvT[n * 100 + d] * qkvT[(8 + j) * 100 + d];
            float e = __expf(2.f * p);
            float tv = 1.f - 2.f / (e + 1.f);
            tdup[idx] = pk2(tv, tv);
        }
        __syncthreads();

        // op6: Gpart (16 groups x 48 nd, 2 f/thread), W2 pre-packed
        {
            ull acc[8];
#pragma unroll
            for (int j = 0; j < 8; ++j) acc[j] = 0ull;
            const ull* w2p = g_W2p + (size_t)(g16 * 48) * 48 + fp48;
            const ulonglong2* tp = (const ulonglong2*)&tdup[(g16 * 48) * 8];
#pragma unroll 4
            for (int m = 0; m < 48; ++m) {
                ull w01 = w2p[(size_t)m * 48];
                ulonglong2 t01 = tp[m * 4 + 0];
                ulonglong2 t23 = tp[m * 4 + 1];
                ulonglong2 t45 = tp[m * 4 + 2];
                ulonglong2 t67 = tp[m * 4 + 3];
                fma2(acc[0], t01.x, w01); fma2(acc[1], t01.y, w01);
                fma2(acc[2], t23.x, w01); fma2(acc[3], t23.y, w01);
                fma2(acc[4], t45.x, w01); fma2(acc[5], t45.y, w01);
                fma2(acc[6], t67.x, w01); fma2(acc[7], t67.y, w01);
            }
#pragma unroll
            for (int j = 0; j < 8; ++j)
                *(ull*)&Gpart[g16 * 768 + j * 96 + e0p] = acc[j];
        }
        __syncthreads();
        {
            float s = Gpart[tid];
#pragma unroll
            for (int g2 = 1; g2 < 16; ++g2) s += Gpart[g2 * 768 + tid];
            __syncthreads();
            Gpart[tid] = s;
        }
        __syncthreads();

        // op7: Mi += a3*(v^T G + b2)
        {
            ull vp[8];
#pragma unroll
            for (int j = 0; j < 8; ++j) {
                float ve = qkvT[(16 + j) * 100 + e7];
                vp[j] = pk2(ve, ve);
            }
#pragma unroll 3
            for (int q = 0; q < 6; ++q) {
                int f0 = f0b7 + q * 2;
                ull acc = 0ull;
#pragma unroll
                for (int j = 0; j < 8; ++j)
                    fma2(acc, vp[j], *(const ull*)&Gpart[j * 96 + f0]);
                float lo, hi;
                upk2(lo, hi, acc);
                Mi[e7 * 100 + f0]     = fmaf(a3v, lo + b2s[f0],     Mi[e7 * 100 + f0]);
                Mi[e7 * 100 + f0 + 1] = fmaf(a3v, hi + b2s[f0 + 1], Mi[e7 * 100 + f0 + 1]);
            }
        }

        // op8: R0 -> bf16 hi/lo; relsum = a1*relsum + sum_n R0
        {
            ull vP[8];
#pragma unroll
            for (int j = 0; j < 8; ++j)
                vP[j] = *(const ull*)&qkvT[(16 + j) * 100 + e0p];
            const size_t mrow = (size_t)(t * 128 + b) * RELK;
            ull racc[6];
#pragma unroll
            for (int mm = 0; mm < 6; ++mm) racc[mm] = 0ull;
#pragma unroll 4
            for (int it = g16; it < 768; it += 16) {
                const ulonglong2* tp = (const ulonglong2*)&tdup[it * 8];
                ulonglong2 t01 = tp[0], t23 = tp[1], t45 = tp[2], t67 = tp[3];
                ull a0 = 0ull;
                fma2(a0, t01.x, vP[0]); fma2(a0, t01.y, vP[1]);
                fma2(a0, t23.x, vP[2]); fma2(a0, t23.y, vP[3]);
                fma2(a0, t45.x, vP[4]); fma2(a0, t45.y, vP[5]);
                fma2(a0, t67.x, vP[6]); fma2(a0, t67.y, vP[7]);
                float f0, f1;
                upk2(f0, f1, a0);
                __nv_bfloat162 h01 = __floats2bfloat162_rn(f0, f1);
                float2 hf01 = __bfloat1622float2(h01);
                __nv_bfloat162 l01 = __floats2bfloat162_rn(f0 - hf01.x, f1 - hf01.y);
                *(uint32_t*)&g_Ahi[mrow + (size_t)it * 96 + e0p] = *(uint32_t*)&h01;
                *(uint32_t*)&g_Alo[mrow + (size_t)it * 96 + e0p] = *(uint32_t*)&l01;
                int mm = (it >> 4) % 6;
                add2(racc[mm], a0);
            }
            const ull a1P = pk2(a1v, a1v);
#pragma unroll
            for (int mm = 0; mm < 6; ++mm) {
                int d = g16 + 16 * mm;
                ull old = *(const ull*)&relsum[d * 96 + e0p];
                fma2(racc[mm], a1P, old);
                *(ull*)&relsum[d * 96 + e0p] = racc[mm];
            }
        }

        // GW partials (independent of op7/op8): GWP[qq][j,h] over f-quarter
        {
            float acc = 0.f;
            const int fb = qq * 24;
#pragma unroll 6
            for (int ff = 0; ff < 24; ++ff)
                acc = fmaf(Gpart[jj * 96 + fb + ff], WqT[hh24 * 100 + fb + ff], acc);
            GWP[qq * 192 + jh] = acc;
        }
        __syncthreads();
        if (tid < 192)
            GW[tid] = GWP[tid] + GWP[192 + tid] + GWP[384 + tid] + GWP[576 + tid];
        __syncthreads();

        // P += a3*(v⊗GW + 1⊗b2W)
        {
            float ve[8];
#pragma unroll
            for (int j = 0; j < 8; ++j) ve[j] = qkvT[(16 + j) * 100 + f96];
#pragma unroll
            for (int hh = 0; hh < 3; ++hh) {
                int h = h0 + hh;
                float acc = b2w[h];
#pragma unroll
                for (int j = 0; j < 8; ++j)
                    acc = fmaf(ve[j], GW[j * 24 + h], acc);
                P[h * 100 + f96] = fmaf(a3v, acc, P[h * 100 + f96]);
            }
        }
        __syncthreads();
    }
}

// ---------------- phase 2: HMMA bf16 GEMM, cp.async double-buffered ----------
#define HB_A_HI 0
#define HB_A_LO 16384
#define HB_B_HI 32768
#define HB_B_LO 40960
#define HB_STRIDE 49152
#define HB_SMEM (2 * HB_STRIDE)   // 98304
#define HB_CHUNKS 24

__device__ __forceinline__ void ldsm4(uint32_t* f, uint32_t addr) {
    asm volatile("ldmatrix.sync.aligned.m8n8.x4.shared.b16 {%0,%1,%2,%3}, [%4];"
                 : "=r"(f[0]), "=r"(f[1]), "=r"(f[2]), "=r"(f[3]) : "r"(addr));
}
__device__ __forceinline__ void mma16816(float* c, const uint32_t* a,
                                         uint32_t b0, uint32_t b1) {
    asm volatile(
        "mma.sync.aligned.m16n8k16.row.col.f32.bf16.bf16.f32 "
        "{%0,%1,%2,%3}, {%4,%5,%6,%7}, {%8,%9}, {%0,%1,%2,%3};"
        : "+f"(c[0]), "+f"(c[1]), "+f"(c[2]), "+f"(c[3])
        : "r"(a[0]), "r"(a[1]), "r"(a[2]), "r"(a[3]), "r"(b0), "r"(b1));
}

__global__ void __launch_bounds__(256) hmma_gemm_kernel() {
    extern __shared__ char smc[];
    const uint32_t sbase = smem_u32(smc);
    const int tid = threadIdx.x;
    const int wid = tid >> 5, lane = tid & 31;
    const int m0 = blockIdx.x * 128;
    const size_t k0 = (size_t)blockIdx.y * 1536;
    const int rit = lane & 7, ti = lane >> 3;

    const int lr = tid >> 3, lq = tid & 7;
    const uint32_t lso = (uint32_t)(((lq ^ (lr & 7)) << 4));

    float acc[8][4];
#pragma unroll
    for (int i = 0; i < 8; ++i)
#pragma unroll
        for (int j = 0; j < 4; ++j) acc[i][j] = 0.f;

    auto issue_chunk = [&](int ch, int sel) {
        const size_t kc = k0 + (size_t)ch * 64;
        const uint32_t bb = sbase + sel * HB_STRIDE;
#pragma unroll
        for (int it = 0; it < 4; ++it) {
            int r = lr + it * 32;
            size_t goff = (size_t)(m0 + r) * RELK + kc + lq * 8;
            uint32_t so = (uint32_t)(r * 128) + lso;
            cpa16(bb + HB_A_HI + so, &g_Ahi[goff]);
            cpa16(bb + HB_A_LO + so, &g_Alo[goff]);
        }
        if (tid < 128) {
#pragma unroll
            for (int it = 0; it < 2; ++it) {
                int idx = it * 128 + tid;
                int r = idx >> 3, q = idx & 7;
                size_t goff = (size_t)r * RELK + kc + q * 8;
                uint32_t so = (uint32_t)(r * 128 + ((q ^ (r & 7)) << 4));
                cpa16(bb + HB_B_HI + so, &g_Bhi[goff]);
                cpa16(bb + HB_B_LO + so, &g_Blo[goff]);
            }
        } else {
#pragma unroll
            for (int it = 0; it < 2; ++it) {
                int idx = it * 128 + (tid - 128) + 256;
                int r = idx >> 3, q = idx & 7;
                size_t goff = (size_t)r * RELK + kc + q * 8;
                uint32_t so = (uint32_t)(r * 128 + ((q ^ (r & 7)) << 4));
                cpa16(bb + HB_B_HI + so, &g_Bhi[goff]);
                cpa16(bb + HB_B_LO + so, &g_Blo[goff]);
            }
        }
        asm volatile("cp.async.commit_group;" ::: "memory");
    };

    issue_chunk(0, 0);
    for (int ch = 0; ch < HB_CHUNKS; ++ch) {
        if (ch + 1 < HB_CHUNKS) {
            issue_chunk(ch + 1, (ch + 1) & 1);
            asm volatile("cp.async.wait_group 1;" ::: "memory");
        } else {
            asm volatile("cp.async.wait_group 0;" ::: "memory");
        }
        __syncthreads();

        const uint32_t bb = sbase + (ch & 1) * HB_STRIDE;
#pragma unroll
        for (int ks = 0; ks < 4; ++ks) {
            uint32_t ahi[4], alo[4];
            {
                int r  = (wid << 4) + ((ti & 1) << 3) + rit;
                int kb = 2 * ks + (ti >> 1);
                uint32_t so = (uint32_t)(r * 128 + ((kb ^ (r & 7)) << 4));
                ldsm4(ahi, bb + HB_A_HI + so);
                ldsm4(alo, bb + HB_A_LO + so);
            }
#pragma unroll
            for (int nt2 = 0; nt2 < 4; ++nt2) {
                uint32_t bhi[4], blo[4];
                int n  = (nt2 << 4) + ((ti >> 1) << 3) + rit;
                int kb = 2 * ks + (ti & 1);
                uint32_t so = (uint32_t)(n * 128 + ((kb ^ (n & 7)) << 4));
                ldsm4(bhi, bb + HB_B_HI + so);
                ldsm4(blo, bb + HB_B_LO + so);
                mma16816(acc[2 * nt2], ahi, bhi[0], bhi[1]);
                mma16816(acc[2 * nt2], ahi, blo[0], blo[1]);
                mma16816(acc[2 * nt2], alo, bhi[0], bhi[1]);
                mma16816(acc[2 * nt2 + 1], ahi, bhi[2], bhi[3]);
                mma16816(acc[2 * nt2 + 1], ahi, blo[2], blo[3]);
                mma16816(acc[2 * nt2 + 1], alo, bhi[2], bhi[3]);
            }
        }
        __syncthreads();
    }

    const int grp = lane >> 2, tig = lane & 3;
    const int m = m0 + wid * 16 + grp;
#pragma unroll
    for (int nt = 0; nt < 8; ++nt) {
        int o = nt * 8 + 2 * tig;
        atomicAdd(&g_zbuf[(size_t)m * 64 + o],           acc[nt][0]);
        atomicAdd(&g_zbuf[(size_t)m * 64 + o + 1],       acc[nt][1]);
        atomicAdd(&g_zbuf[(size_t)(m + 8) * 64 + o],     acc[nt][2]);
        atomicAdd(&g_zbuf[(size_t)(m + 8) * 64 + o + 1], acc[nt][3]);
    }
}

__global__ void scan_kernel(float* __restrict__ out, const float* __restrict__ pa1) {
    const int b = blockIdx.x;
    const int o = threadIdx.x;
    const float a1v = *pa1;
    const float z0o = g_z0[o], cc = g_cconst[o];
    float acc = 0.f, p = 1.f;
#pragma unroll
    for (int t = 0; t < 16; ++t) {
        p *= a1v;
        acc = fmaf(a1v, acc, g_zbuf[(size_t)(t * 128 + b) * 64 + o]);
        out[(size_t)(t * 128 + b) * 64 + o] = fmaf(p, z0o, acc + cc);
    }
}

extern "C" void kernel_launch(void* const* d_in, const int* in_sizes, int n_in,
                              void* d_out, int out_size) {
    const float* x         = (const float*)d_in[0];
    const float* Wqkv      = (const float*)d_in[1];
    const float* bqkv      = (const float*)d_in[2];
    const float* ln_g      = (const float*)d_in[3];
    const float* ln_b      = (const float*)d_in[4];
    const float* a1        = (const float*)d_in[5];
    const float* a2        = (const float*)d_in[6];
    const float* a3        = (const float*)d_in[7];
    const float* W2        = (const float*)d_in[8];
    const float* b2        = (const float*)d_in[9];
    const float* Wr        = (const float*)d_in[10];
    const float* br        = (const float*)d_in[11];
    const float* W3        = (const float*)d_in[12];
    const float* b3        = (const float*)d_in[13];
    const float* item_bias = (const float*)d_in[14];
    const float* rel_bias  = (const float*)d_in[15];
    float* out = (float*)d_out;

    cudaFuncSetAttribute(step_kernel, cudaFuncAttributeMaxDynamicSharedMemorySize,
                         STEP_SMEM_BYTES);
    cudaFuncSetAttribute(hmma_gemm_kernel, cudaFuncAttributeMaxDynamicSharedMemorySize,
                         HB_SMEM);

    init_kernel<<<512, 256>>>(rel_bias, W2);                                    // 1
    c2_kernel<<<dim3(288, 8), 256>>>(Wr, W3, rel_bias);                         // 2
    cconst_kernel<<<1, 64>>>(br, W3, b3);                                       // 3
    step_kernel<<<128, 768, STEP_SMEM_BYTES>>>(x, Wqkv, bqkv, ln_g, ln_b,
                                               a1, a2, a3, b2, item_bias);      // 4 (profiled)
    hmma_gemm_kernel<<<dim3(16, 48), 256, HB_SMEM>>>();                         // 5
    scan_kernel<<<128, 64>>>(out, a1);                                          // 6
}

// round 17
// speedup vs baseline: 2.4164x; 1.1503x over previous
#include <cuda_runtime.h>
#include <cuda_bf16.h>
#include <cstdint>

typedef unsigned long long ull;

#define RELK 73728

// ---------------- smem layout for step_kernel (float offsets), 768 threads ---
#define SM_MI     0        // 9600 (96x100)
#define SM_RELSUM 9600     // 9216
#define SM_TDUP   18816    // 12288 (6144 ull)
#define SM_QKVT   31104    // 2400 (24x100)
#define SM_WQT    33504    // 2400
#define SM_LG     35904    // 2304
#define SM_LB     38208    // 2304
#define SM_GPART  40512    // 12288 (16x768)
#define SM_P      52800    // 2400 (24x100)  qkv-pre = Mi@Wqkv
#define SM_GWP    55200    // 768 (4x192)
#define SM_GW     55968    // 192
#define SM_XTS    56160    // 96
#define SM_VTR8   56256    // 768
#define SM_VTRF   57024    // 96
#define SM_XW     57120    // 32
#define SM_BQ     57152    // 32
#define SM_B2S    57184    // 96
#define SM_B2W    57280    // 32
#define SM_RED    57312    // 64
#define STEP_SMEM_FLOATS 57376
#define STEP_SMEM_BYTES (STEP_SMEM_FLOATS * 4)   // 229,504 B

// ---------------- device scratch (allocation-free rule) ----------------
__device__ float g_C2[(size_t)8 * 9216 * 64];                  // 18.9MB
__device__ float g_cconst[64];
__device__ float g_relsum0[9216];
__device__ float g_z0[64];
__device__ float g_zbuf[(size_t)2048 * 64];
__device__ ull   g_W2p[(size_t)768 * 48];                      // (w,w) pairs, 294KB
__device__ __nv_bfloat16 g_Ahi[(size_t)2048 * RELK];           // 302MB
__device__ __nv_bfloat16 g_Alo[(size_t)2048 * RELK];           // 302MB
__device__ __nv_bfloat16 g_Bhi[(size_t)64 * RELK];             // 9.4MB  [o][k]
__device__ __nv_bfloat16 g_Blo[(size_t)64 * RELK];             // 9.4MB

// ---------------- f32x2 packed helpers ----------------
__device__ __forceinline__ ull pk2(float x, float y) {
    ull r;
    asm("mov.b64 %0, {%1, %2};" : "=l"(r) : "f"(x), "f"(y));
    return r;
}
__device__ __forceinline__ void fma2(ull& d, ull a, ull b) {
    asm("fma.rn.f32x2 %0, %1, %2, %0;" : "+l"(d) : "l"(a), "l"(b));
}
__device__ __forceinline__ void add2(ull& d, ull a) {
    asm("add.rn.f32x2 %0, %0, %1;" : "+l"(d) : "l"(a));
}
__device__ __forceinline__ void upk2(float& lo, float& hi, ull v) {
    asm("mov.b64 {%0, %1}, %2;" : "=f"(lo), "=f"(hi) : "l"(v));
}
__device__ __forceinline__ uint32_t smem_u32(const void* p) {
    uint32_t a;
    asm("{ .reg .u64 t; cvta.to.shared.u64 t, %1; cvt.u32.u64 %0, t; }"
        : "=r"(a) : "l"(p));
    return a;
}
__device__ __forceinline__ void cpa16(uint32_t dst, const void* src) {
    asm volatile("cp.async.cg.shared.global [%0], [%1], 16;"
                 :: "r"(dst), "l"(__cvta_generic_to_global(src)) : "memory");
}

// ---- combined init: relsum0, zbuf, z0, W2 pack (launch #1) ----
__global__ void init_kernel(const float* __restrict__ rb,
                            const float* __restrict__ W2) {
    int idx = blockIdx.x * 256 + threadIdx.x;   // grid 512 -> 131072
    if (idx < 9216) {
        float s = 0.f;
#pragma unroll
        for (int n = 0; n < 8; ++n) s += rb[n * 9216 + idx];
        g_relsum0[idx] = s;
    }
    g_zbuf[idx] = 0.f;
    if (idx < 64) g_z0[idx] = 0.f;
    if (idx < 36864) {
        int row = idx / 48, fp = idx % 48;
        float2 w = *(const float2*)&W2[row * 96 + 2 * fp];
        g_W2p[idx] = pk2(w.x, w.y);
    }
}

// ---- C2 build + transposed bf16 hi/lo + z0 partials (launch #2) ----
__global__ void __launch_bounds__(256, 1) c2_kernel(const float* __restrict__ Wr,
                                                    const float* __restrict__ W3,
                                                    const float* __restrict__ rb) {
    __shared__ float Wrs[32 * 96];
    __shared__ float W3s[96 * 64];
    __shared__ float smt[32][65];
    __shared__ float zz[256];
    const int tid = threadIdx.x;
    const int de0 = blockIdx.x * 32;   // 288 de-tiles
    const int n = blockIdx.y;          // 8
    for (int p = tid; p < 3072; p += 256) Wrs[p] = Wr[de0 * 96 + p];
    for (int p = tid; p < 6144; p += 256) W3s[p] = W3[n * 6144 + p];
    __syncthreads();
    const int o = tid & 63, de_b = tid >> 6;
    float acc[8];
#pragma unroll
    for (int i = 0; i < 8; ++i) acc[i] = 0.f;
    for (int r = 0; r < 96; ++r) {
        float bv = W3s[r * 64 + o];
#pragma unroll
        for (int i = 0; i < 8; ++i)
            acc[i] = fmaf(Wrs[(de_b + 4 * i) * 96 + r], bv, acc[i]);
    }
    float zp = 0.f;
#pragma unroll
    for (int i = 0; i < 8; ++i) {
        int de = de0 + de_b + 4 * i;
        g_C2[((size_t)n * 9216 + de) * 64 + o] = acc[i];
        smt[de_b + 4 * i][o] = acc[i];
        zp = fmaf(rb[n * 9216 + de], acc[i], zp);
    }
    zz[tid] = zp;
    __syncthreads();
    if (tid < 64) {
        float s = zz[o] + zz[64 + o] + zz[128 + o] + zz[192 + o];
        atomicAdd(&g_z0[o], s);
    }
    {
        const int o2 = tid >> 2, seg = tid & 3;
        float v[8];
#pragma unroll
        for (int r = 0; r < 8; ++r) v[r] = smt[seg * 8 + r][o2];
        uint32_t hw[4], lw[4];
#pragma unroll
        for (int p = 0; p < 4; ++p) {
            __nv_bfloat162 h = __floats2bfloat162_rn(v[2 * p], v[2 * p + 1]);
            float2 hf = __bfloat1622float2(h);
            __nv_bfloat162 l = __floats2bfloat162_rn(v[2 * p] - hf.x,
                                                     v[2 * p + 1] - hf.y);
            hw[p] = *(uint32_t*)&h;
            lw[p] = *(uint32_t*)&l;
        }
        size_t base = (size_t)o2 * RELK + (size_t)n * 9216 + de0 + seg * 8;
        *(uint4*)&g_Bhi[base] = make_uint4(hw[0], hw[1], hw[2], hw[3]);
        *(uint4*)&g_Blo[base] = make_uint4(lw[0], lw[1], lw[2], lw[3]);
    }
}

__global__ void cconst_kernel(const float* __restrict__ br,
                              const float* __restrict__ W3,
                              const float* __restrict__ b3) {
    int o = threadIdx.x;
    float acc = b3[o];
    for (int nr = 0; nr < 768; ++nr)
        acc = fmaf(br[nr % 96], W3[nr * 64 + o], acc);
    g_cconst[o] = acc;
}

// ---------------- phase 1: recurrent kernel, 768 threads (launch #4) ---------
__global__ void __launch_bounds__(768, 1) step_kernel(
    const float* __restrict__ x, const float* __restrict__ Wqkv,
    const float* __restrict__ bqkv, const float* __restrict__ ln_g,
    const float* __restrict__ ln_b, const float* __restrict__ pa1,
    const float* __restrict__ pa2, const float* __restrict__ pa3,
    const float* __restrict__ b2, const float* __restrict__ item_bias)
{
    extern __shared__ float sm[];
    float* Mi     = sm + SM_MI;
    float* relsum = sm + SM_RELSUM;
    ull*   tdup   = (ull*)(sm + SM_TDUP);
    float* qkvT   = sm + SM_QKVT;
    float* WqT    = sm + SM_WQT;
    float* lg     = sm + SM_LG;
    float* lb     = sm + SM_LB;
    float* Gpart  = sm + SM_GPART;
    float* P      = sm + SM_P;
    float* GWP    = sm + SM_GWP;
    float* GW     = sm + SM_GW;
    float* xts    = sm + SM_XTS;
    float* vtr8   = sm + SM_VTR8;
    float* vtrF   = sm + SM_VTRF;
    float* xw     = sm + SM_XW;
    float* bq     = sm + SM_BQ;
    float* b2s    = sm + SM_B2S;
    float* b2w    = sm + SM_B2W;
    float* red    = sm + SM_RED;

    const int tid = threadIdx.x;
    const int b = blockIdx.x;
    const float a1v = *pa1, a2v = *pa2, a3v = *pa3;

    // hoisted per-thread indices
    const int f96 = tid % 96, q8 = tid / 96;
    const int h0  = q8 * 3;
    const int d0v = q8 * 12;
    const int fp48 = tid % 48, g16 = tid / 48;   // fused op6/op8 lane maps
    const int e0p = 2 * fp48;
    const int jh = tid % 192, qq = tid / 192;    // GW partials
    const int jj = jh / 24, hh24 = jh % 24;
    const int e7 = tid >> 3, part7 = tid & 7;    // op7
    const int f0b7 = part7 * 12;
    // fused-loop base pointers (advance per t only by mrow)
    const ulonglong2* tp0 = ((const ulonglong2*)tdup) + g16 * 4;
    const ull* wp0 = g_W2p + (size_t)g16 * 48 + fp48;

    // one-time loads
    for (int idx = tid; idx < 2304; idx += 768) {
        int f = idx / 24, h = idx % 24;
        WqT[h * 100 + f] = Wqkv[idx];
        lg[idx] = ln_g[idx];
        lb[idx] = ln_b[idx];
    }
    if (tid < 24) bq[tid] = bqkv[tid];
    if (tid < 96) b2s[tid] = b2[tid];
    for (int idx = tid; idx < 9216; idx += 768) {
        Mi[(idx / 96) * 100 + (idx % 96)] = item_bias[idx];
        relsum[idx] = g_relsum0[idx];
    }
    __syncthreads();

    // one-time: P = Mi@Wqkv, b2W
    {
        ull acc2[3][2];
#pragma unroll
        for (int i = 0; i < 3; ++i) { acc2[i][0] = 0ull; acc2[i][1] = 0ull; }
#pragma unroll 6
        for (int fq = 0; fq < 24; ++fq) {
            ulonglong2 m2 = *(const ulonglong2*)&Mi[f96 * 100 + 4 * fq];
#pragma unroll
            for (int hh = 0; hh < 3; ++hh) {
                ulonglong2 w2v = *(const ulonglong2*)&WqT[(h0 + hh) * 100 + 4 * fq];
                fma2(acc2[hh][0], m2.x, w2v.x);
                fma2(acc2[hh][1], m2.y, w2v.y);
            }
        }
#pragma unroll
        for (int hh = 0; hh < 3; ++hh) {
            float l0, h0f, l1, h1f;
            upk2(l0, h0f, acc2[hh][0]);
            upk2(l1, h1f, acc2[hh][1]);
            P[(h0 + hh) * 100 + f96] = (l0 + h0f) + (l1 + h1f);
        }
    }
    if (tid < 24) {
        float acc = 0.f;
        for (int f = 0; f < 96; ++f)
            acc = fmaf(b2s[f], WqT[tid * 100 + f], acc);
        b2w[tid] = acc;
    }
    __syncthreads();

    for (int t = 0; t < 16; ++t) {
        if (tid < 96) xts[tid] = x[(t * 128 + b) * 96 + tid];
        __syncthreads();

        // fused op1 + Vtr partials
        {
            float accv = 0.f;
            const float xf = xts[f96];
#pragma unroll 4
            for (int d = d0v; d < d0v + 12; ++d) {
                float m = fmaf(xts[d], xf, Mi[d * 100 + f96]);
                Mi[d * 100 + f96] = m;
                accv = fmaf(m, relsum[d * 96 + f96], accv);
            }
            vtr8[q8 * 96 + f96] = accv;
        }
        if (tid < 24) {
            float acc = 0.f;
            for (int f = 0; f < 96; ++f)
                acc = fmaf(xts[f], WqT[tid * 100 + f], acc);
            xw[tid] = acc;
        }
        __syncthreads();
        if (tid < 96) {
            float s = vtr8[tid];
#pragma unroll
            for (int q = 1; q < 8; ++q) s += vtr8[q * 96 + tid];
            vtrF[tid] = s;
        }
        __syncthreads();

        // qkv from incremental P
        float s1 = 0.f, s2 = 0.f;
        {
            const float xd = xts[f96];
            const float vtrd = vtrF[f96];
#pragma unroll
            for (int hh = 0; hh < 3; ++hh) {
                int h = h0 + hh;
                float xwh = xw[h];
                float Pv = fmaf(xd, xwh, P[h * 100 + f96]);
                P[h * 100 + f96] = Pv;
                float v = Pv + bq[h] + a2v * vtrd * xwh;
                qkvT[h * 100 + f96] = v;
                s1 += v;
                s2 = fmaf(v, v, s2);
            }
        }
#pragma unroll
        for (int o = 16; o > 0; o >>= 1) {
            s1 += __shfl_down_sync(0xffffffffu, s1, o);
            s2 += __shfl_down_sync(0xffffffffu, s2, o);
        }
        if ((tid & 31) == 0) { red[(tid >> 5) * 2] = s1; red[(tid >> 5) * 2 + 1] = s2; }
        __syncthreads();
        if (tid == 0) {
            float S = 0.f, SS = 0.f;
            for (int w = 0; w < 24; ++w) { S += red[w * 2]; SS += red[w * 2 + 1]; }
            float mu = S * (1.f / 2304.f);
            float var = SS * (1.f / 2304.f) - mu * mu;
            red[62] = mu;
            red[63] = rsqrtf(var + 1e-5f);
        }
        __syncthreads();
        const float mu = red[62], rstd = red[63];

        // LN apply
        for (int idx = tid; idx < 2304; idx += 768) {
            int h = idx / 96, d = idx % 96;
            float v = qkvT[h * 100 + d];
            qkvT[h * 100 + d] = (v - mu) * rstd * lg[d * 24 + h] + lb[d * 24 + h];
        }
        __syncthreads();

        // op5: tdup
        for (int idx = tid; idx < 6144; idx += 768) {
            int j = idx & 7, d = (idx >> 3) % 96, n = idx / 768;
            float p = qkvT[n * 100 + d] * qkvT[(8 + j) * 100 + d];
            float e = __expf(2.f * p);
            float tv = 1.f - 2.f / (e + 1.f);
            tdup[idx] = pk2(tv, tv);
        }
        __syncthreads();

        // FUSED op6+op8: single tdup pass.
        // it = g16 + 16*m; accG = strided Gpart partial; a0 = R0 e-pair;
        // relsum d = g16 + 16*(m%6).
        {
            ull accG[8], racc[6], vP[8];
#pragma unroll
            for (int j = 0; j < 8; ++j) accG[j] = 0ull;
#pragma unroll
            for (int mm = 0; mm < 6; ++mm) racc[mm] = 0ull;
#pragma unroll
            for (int j = 0; j < 8; ++j)
                vP[j] = *(const ull*)&qkvT[(16 + j) * 100 + e0p];
            const size_t mrow = (size_t)(t * 128 + b) * RELK;
            uint32_t* ahip = (uint32_t*)&g_Ahi[mrow + (size_t)g16 * 96 + e0p];
            uint32_t* alop = (uint32_t*)&g_Alo[mrow + (size_t)g16 * 96 + e0p];
#pragma unroll 6
            for (int m = 0; m < 48; ++m) {
                const ulonglong2* tp = tp0 + 64 * m;
                ulonglong2 t01 = tp[0], t23 = tp[1], t45 = tp[2], t67 = tp[3];
                ull w = wp0[768 * m];
                fma2(accG[0], t01.x, w); fma2(accG[1], t01.y, w);
                fma2(accG[2], t23.x, w); fma2(accG[3], t23.y, w);
                fma2(accG[4], t45.x, w); fma2(accG[5], t45.y, w);
                fma2(accG[6], t67.x, w); fma2(accG[7], t67.y, w);
                ull a0 = 0ull;
                fma2(a0, t01.x, vP[0]); fma2(a0, t01.y, vP[1]);
                fma2(a0, t23.x, vP[2]); fma2(a0, t23.y, vP[3]);
                fma2(a0, t45.x, vP[4]); fma2(a0, t45.y, vP[5]);
                fma2(a0, t67.x, vP[6]); fma2(a0, t67.y, vP[7]);
                float f0, f1;
                upk2(f0, f1, a0);
                __nv_bfloat162 h01 = __floats2bfloat162_rn(f0, f1);
                float2 hf01 = __bfloat1622float2(h01);
                __nv_bfloat162 l01 = __floats2bfloat162_rn(f0 - hf01.x, f1 - hf01.y);
                ahip[768 * m] = *(uint32_t*)&h01;
                alop[768 * m] = *(uint32_t*)&l01;
                add2(racc[m % 6], a0);
            }
#pragma unroll
            for (int j = 0; j < 8; ++j)
                *(ull*)&Gpart[g16 * 768 + j * 96 + e0p] = accG[j];
            const ull a1P = pk2(a1v, a1v);
#pragma unroll
            for (int mm = 0; mm < 6; ++mm) {
                int d = g16 + 16 * mm;
                ull old = *(const ull*)&relsum[d * 96 + e0p];
                fma2(racc[mm], a1P, old);
                *(ull*)&relsum[d * 96 + e0p] = racc[mm];
            }
        }
        __syncthreads();
        // reduce 16 Gpart partials -> G
        {
            float s = Gpart[tid];
#pragma unroll
            for (int g2 = 1; g2 < 16; ++g2) s += Gpart[g2 * 768 + tid];
            __syncthreads();
            Gpart[tid] = s;
        }
        __syncthreads();

        // op7: Mi += a3*(v^T G + b2)
        {
            ull vp[8];
#pragma unroll
            for (int j = 0; j < 8; ++j) {
                float ve = qkvT[(16 + j) * 100 + e7];
                vp[j] = pk2(ve, ve);
            }
#pragma unroll 3
            for (int q = 0; q < 6; ++q) {
                int f0 = f0b7 + q * 2;
                ull acc = 0ull;
#pragma unroll
                for (int j = 0; j < 8; ++j)
                    fma2(acc, vp[j], *(const ull*)&Gpart[j * 96 + f0]);
                float lo, hi;
                upk2(lo, hi, acc);
                Mi[e7 * 100 + f0]     = fmaf(a3v, lo + b2s[f0],     Mi[e7 * 100 + f0]);
                Mi[e7 * 100 + f0 + 1] = fmaf(a3v, hi + b2s[f0 + 1], Mi[e7 * 100 + f0 + 1]);
            }
        }

        // GW partials
        {
            float acc = 0.f;
            const int fb = qq * 24;
#pragma unroll 6
            for (int ff = 0; ff < 24; ++ff)
                acc = fmaf(Gpart[jj * 96 + fb + ff], WqT[hh24 * 100 + fb + ff], acc);
            GWP[qq * 192 + jh] = acc;
        }
        __syncthreads();
        if (tid < 192)
            GW[tid] = GWP[tid] + GWP[192 + tid] + GWP[384 + tid] + GWP[576 + tid];
        __syncthreads();

        // P += a3*(v⊗GW + 1⊗b2W)
        {
            float ve[8];
#pragma unroll
            for (int j = 0; j < 8; ++j) ve[j] = qkvT[(16 + j) * 100 + f96];
#pragma unroll
            for (int hh = 0; hh < 3; ++hh) {
                int h = h0 + hh;
                float acc = b2w[h];
#pragma unroll
                for (int j = 0; j < 8; ++j)
                    acc = fmaf(ve[j], GW[j * 24 + h], acc);
                P[h * 100 + f96] = fmaf(a3v, acc, P[h * 100 + f96]);
            }
        }
        __syncthreads();
    }
}

// ---------------- phase 2: HMMA bf16 GEMM, cp.async double-buffered ----------
#define HB_A_HI 0
#define HB_A_LO 16384
#define HB_B_HI 32768
#define HB_B_LO 40960
#define HB_STRIDE 49152
#define HB_SMEM (2 * HB_STRIDE)   // 98304
#define HB_CHUNKS 24

__device__ __forceinline__ void ldsm4(uint32_t* f, uint32_t addr) {
    asm volatile("ldmatrix.sync.aligned.m8n8.x4.shared.b16 {%0,%1,%2,%3}, [%4];"
                 : "=r"(f[0]), "=r"(f[1]), "=r"(f[2]), "=r"(f[3]) : "r"(addr));
}
__device__ __forceinline__ void mma16816(float* c, const uint32_t* a,
                                         uint32_t b0, uint32_t b1) {
    asm volatile(
        "mma.sync.aligned.m16n8k16.row.col.f32.bf16.bf16.f32 "
        "{%0,%1,%2,%3}, {%4,%5,%6,%7}, {%8,%9}, {%0,%1,%2,%3};"
        : "+f"(c[0]), "+f"(c[1]), "+f"(c[2]), "+f"(c[3])
        : "r"(a[0]), "r"(a[1]), "r"(a[2]), "r"(a[3]), "r"(b0), "r"(b1));
}

__global__ void __launch_bounds__(256) hmma_gemm_kernel() {
    extern __shared__ char smc[];
    const uint32_t sbase = smem_u32(smc);
    const int tid = threadIdx.x;
    const int wid = tid >> 5, lane = tid & 31;
    const int m0 = blockIdx.x * 128;
    const size_t k0 = (size_t)blockIdx.y * 1536;
    const int rit = lane & 7, ti = lane >> 3;

    const int lr = tid >> 3, lq = tid & 7;
    const uint32_t lso = (uint32_t)(((lq ^ (lr & 7)) << 4));

    float acc[8][4];
#pragma unroll
    for (int i = 0; i < 8; ++i)
#pragma unroll
        for (int j = 0; j < 4; ++j) acc[i][j] = 0.f;

    auto issue_chunk = [&](int ch, int sel) {
        const size_t kc = k0 + (size_t)ch * 64;
        const uint32_t bb = sbase + sel * HB_STRIDE;
#pragma unroll
        for (int it = 0; it < 4; ++it) {
            int r = lr + it * 32;
            size_t goff = (size_t)(m0 + r) * RELK + kc + lq * 8;
            uint32_t so = (uint32_t)(r * 128) + lso;
            cpa16(bb + HB_A_HI + so, &g_Ahi[goff]);
            cpa16(bb + HB_A_LO + so, &g_Alo[goff]);
        }
        if (tid < 128) {
#pragma unroll
            for (int it = 0; it < 2; ++it) {
                int idx = it * 128 + tid;
                int r = idx >> 3, q = idx & 7;
                size_t goff = (size_t)r * RELK + kc + q * 8;
                uint32_t so = (uint32_t)(r * 128 + ((q ^ (r & 7)) << 4));
                cpa16(bb + HB_B_HI + so, &g_Bhi[goff]);
                cpa16(bb + HB_B_LO + so, &g_Blo[goff]);
            }
        } else {
#pragma unroll
            for (int it = 0; it < 2; ++it) {
                int idx = it * 128 + (tid - 128) + 256;
                int r = idx >> 3, q = idx & 7;
                size_t goff = (size_t)r * RELK + kc + q * 8;
                uint32_t so = (uint32_t)(r * 128 + ((q ^ (r & 7)) << 4));
                cpa16(bb + HB_B_HI + so, &g_Bhi[goff]);
                cpa16(bb + HB_B_LO + so, &g_Blo[goff]);
            }
        }
        asm volatile("cp.async.commit_group;" ::: "memory");
    };

    issue_chunk(0, 0);
    for (int ch = 0; ch < HB_CHUNKS; ++ch) {
        if (ch + 1 < HB_CHUNKS) {
            issue_chunk(ch + 1, (ch + 1) & 1);
            asm volatile("cp.async.wait_group 1;" ::: "memory");
        } else {
            asm volatile("cp.async.wait_group 0;" ::: "memory");
        }
        __syncthreads();

        const uint32_t bb = sbase + (ch & 1) * HB_STRIDE;
#pragma unroll
        for (int ks = 0; ks < 4; ++ks) {
            uint32_t ahi[4], alo[4];
            {
                int r  = (wid << 4) + ((ti & 1) << 3) + rit;
                int kb = 2 * ks + (ti >> 1);
                uint32_t so = (uint32_t)(r * 128 + ((kb ^ (r & 7)) << 4));
                ldsm4(ahi, bb + HB_A_HI + so);
                ldsm4(alo, bb + HB_A_LO + so);
            }
#pragma unroll
            for (int nt2 = 0; nt2 < 4; ++nt2) {
                uint32_t bhi[4], blo[4];
                int n  = (nt2 << 4) + ((ti >> 1) << 3) + rit;
                int kb = 2 * ks + (ti & 1);
                uint32_t so = (uint32_t)(n * 128 + ((kb ^ (n & 7)) << 4));
                ldsm4(bhi, bb + HB_B_HI + so);
                ldsm4(blo, bb + HB_B_LO + so);
                mma16816(acc[2 * nt2], ahi, bhi[0], bhi[1]);
                mma16816(acc[2 * nt2], ahi, blo[0], blo[1]);
                mma16816(acc[2 * nt2], alo, bhi[0], bhi[1]);
                mma16816(acc[2 * nt2 + 1], ahi, bhi[2], bhi[3]);
                mma16816(acc[2 * nt2 + 1], ahi, blo[2], blo[3]);
                mma16816(acc[2 * nt2 + 1], alo, bhi[2], bhi[3]);
            }
        }
        __syncthreads();
    }

    const int grp = lane >> 2, tig = lane & 3;
    const int m = m0 + wid * 16 + grp;
#pragma unroll
    for (int nt = 0; nt < 8; ++nt) {
        int o = nt * 8 + 2 * tig;
        atomicAdd(&g_zbuf[(size_t)m * 64 + o],           acc[nt][0]);
        atomicAdd(&g_zbuf[(size_t)m * 64 + o + 1],       acc[nt][1]);
        atomicAdd(&g_zbuf[(size_t)(m + 8) * 64 + o],     acc[nt][2]);
        atomicAdd(&g_zbuf[(size_t)(m + 8) * 64 + o + 1], acc[nt][3]);
    }
}

__global__ void scan_kernel(float* __restrict__ out, const float* __restrict__ pa1) {
    const int b = blockIdx.x;
    const int o = threadIdx.x;
    const float a1v = *pa1;
    const float z0o = g_z0[o], cc = g_cconst[o];
    float acc = 0.f, p = 1.f;
#pragma unroll
    for (int t = 0; t < 16; ++t) {
        p *= a1v;
        acc = fmaf(a1v, acc, g_zbuf[(size_t)(t * 128 + b) * 64 + o]);
        out[(size_t)(t * 128 + b) * 64 + o] = fmaf(p, z0o, acc + cc);
    }
}

extern "C" void kernel_launch(void* const* d_in, const int* in_sizes, int n_in,
                              void* d_out, int out_size) {
    const float* x         = (const float*)d_in[0];
    const float* Wqkv      = (const float*)d_in[1];
    const float* bqkv      = (const float*)d_in[2];
    const float* ln_g      = (const float*)d_in[3];
    const float* ln_b      = (const float*)d_in[4];
    const float* a1        = (const float*)d_in[5];
    const float* a2        = (const float*)d_in[6];
    const float* a3        = (const float*)d_in[7];
    const float* W2        = (const float*)d_in[8];
    const float* b2        = (const float*)d_in[9];
    const float* Wr        = (const float*)d_in[10];
    const float* br        = (const float*)d_in[11];
    const float* W3        = (const float*)d_in[12];
    const float* b3        = (const float*)d_in[13];
    const float* item_bias = (const float*)d_in[14];
    const float* rel_bias  = (const float*)d_in[15];
    float* out = (float*)d_out;

    cudaFuncSetAttribute(step_kernel, cudaFuncAttributeMaxDynamicSharedMemorySize,
                         STEP_SMEM_BYTES);
    cudaFuncSetAttribute(hmma_gemm_kernel, cudaFuncAttributeMaxDynamicSharedMemorySize,
                         HB_SMEM);

    init_kernel<<<512, 256>>>(rel_bias, W2);                                    // 1
    c2_kernel<<<dim3(288, 8), 256>>>(Wr, W3, rel_bias);                         // 2
    cconst_kernel<<<1, 64>>>(br, W3, b3);                                       // 3
    step_kernel<<<128, 768, STEP_SMEM_BYTES>>>(x, Wqkv, bqkv, ln_g, ln_b,
                                               a1, a2, a3, b2, item_bias);      // 4 (profiled)
    hmma_gemm_kernel<<<dim3(16, 48), 256, HB_SMEM>>>();                         // 5
    scan_kernel<<<128, 64>>>(out, a1);                                          // 6
}